// round 2
// baseline (speedup 1.0000x reference)
#include <cuda_runtime.h>
#include <math.h>

#define NNODES 100000
#define NEDGES 1600000
#define DH 128
#define BN_EPS 1e-5f

// ---------------- scratch (static __device__, no allocs) ----------------
__device__ __align__(16) float g_bufA[(size_t)NNODES * DH];
__device__ __align__(16) float g_bufB[(size_t)NNODES * DH];
__device__ int   g_count[NNODES];
__device__ float g_dinv[NNODES];
__device__ int   g_rowstart[NNODES + 1];
__device__ int   g_cursor[NNODES];
__device__ int   g_col[NEDGES];
__device__ float g_wgt[NEDGES];
__device__ float g_sum1[DH], g_sq1[DH], g_sum2[DH], g_sq2[DH];
__device__ __align__(16) float g_scale[DH], g_shift[DH];
__device__ int   g_psum[128];
__device__ int   g_is64;

// ---------------- edge_index dtype detection (int64 vs int32) ----------------
// jnp.int64 in the reference, but the harness may transport as int32.
// Genuine int64 indices are all < NNODES; int32 data read as int64 packs two
// random indices -> value >= 2^32 almost surely. Sample 8 elements.
__global__ void detect_kernel(const void* ei) {
    const long long* p = (const long long*)ei;
    int ok = 1;
    #pragma unroll
    for (int i = 0; i < 8; i++) {
        long long v = p[i];
        if (v < 0 || v >= NNODES) ok = 0;
    }
    g_is64 = ok;
}

__device__ __forceinline__ int load_idx(const void* ei, long long pos, int is64) {
    return is64 ? (int)((const long long*)ei)[pos] : ((const int*)ei)[pos];
}

// ---------------- utility: block exclusive scan (shfl-based) ----------------
__device__ __forceinline__ int block_excl_scan(int v) {
    const unsigned full = 0xffffffffu;
    int tid = threadIdx.x, lane = tid & 31, wid = tid >> 5;
    int incl = v;
    #pragma unroll
    for (int o = 1; o < 32; o <<= 1) {
        int t = __shfl_up_sync(full, incl, o);
        if (lane >= o) incl += t;
    }
    __shared__ int ws[32];
    if (lane == 31) ws[wid] = incl;
    __syncthreads();
    if (wid == 0) {
        int nw = blockDim.x >> 5;
        int s = (lane < nw) ? ws[lane] : 0;
        #pragma unroll
        for (int o = 1; o < 32; o <<= 1) {
            int t = __shfl_up_sync(full, s, o);
            if (lane >= o) s += t;
        }
        ws[lane] = s;
    }
    __syncthreads();
    int base = wid ? ws[wid - 1] : 0;
    return base + incl - v;
}

// ---------------- graph prep ----------------
__global__ void zero_kernel() {
    int i = blockIdx.x * 256 + threadIdx.x;
    if (i < NNODES) g_count[i] = 0;
    if (i < DH) { g_sum1[i] = 0.f; g_sq1[i] = 0.f; g_sum2[i] = 0.f; g_sq2[i] = 0.f; }
}

__global__ void hist_kernel(const void* __restrict__ ei) {
    int e = blockIdx.x * 256 + threadIdx.x;
    int is64 = g_is64;
    if (e < NEDGES) {
        int d = load_idx(ei, (long long)NEDGES + e, is64);
        atomicAdd(&g_count[d], 1);
    }
}

__global__ void dinv_kernel() {
    int i = blockIdx.x * 256 + threadIdx.x;
    if (i < NNODES) g_dinv[i] = rsqrtf((float)g_count[i] + 1.0f);
}

__global__ void scanA_kernel() {
    int i = blockIdx.x * 1024 + threadIdx.x;
    int v = (i < NNODES) ? g_count[i] : 0;
    const unsigned full = 0xffffffffu;
    #pragma unroll
    for (int o = 16; o; o >>= 1) v += __shfl_down_sync(full, v, o);
    __shared__ int ws[32];
    int lane = threadIdx.x & 31, wid = threadIdx.x >> 5;
    if (lane == 0) ws[wid] = v;
    __syncthreads();
    if (wid == 0) {
        int s = ws[lane];
        #pragma unroll
        for (int o = 16; o; o >>= 1) s += __shfl_down_sync(full, s, o);
        if (lane == 0) g_psum[blockIdx.x] = s;
    }
}

__global__ void scanB_kernel(int nb) {
    int tid = threadIdx.x;
    int v = (tid < nb) ? g_psum[tid] : 0;
    int ex = block_excl_scan(v);
    __syncthreads();
    if (tid < nb) g_psum[tid] = ex;
}

__global__ void scanC_kernel() {
    int i = blockIdx.x * 1024 + threadIdx.x;
    int v = (i < NNODES) ? g_count[i] : 0;
    int ex = block_excl_scan(v) + g_psum[blockIdx.x];
    if (i < NNODES) { g_rowstart[i] = ex; g_cursor[i] = ex; }
    if (i == NNODES - 1) g_rowstart[NNODES] = ex + v;
}

__global__ void fill_kernel(const void* __restrict__ ei) {
    int e = blockIdx.x * 256 + threadIdx.x;
    int is64 = g_is64;
    if (e < NEDGES) {
        int s = load_idx(ei, e, is64);
        int d = load_idx(ei, (long long)NEDGES + e, is64);
        int pos = atomicAdd(&g_cursor[d], 1);
        g_col[pos] = s;
        g_wgt[pos] = g_dinv[s] * g_dinv[d];
    }
}

// ---------------- GEMM: C[N,DOUT] = A[N,DIN] @ W[DIN,DOUT] (+bias,relu) ----------------
template <int DIN, int DOUT, bool BIASRELU>
__global__ void gemm_kernel(const float* __restrict__ A, const float* __restrict__ W,
                            const float* __restrict__ bias, float* __restrict__ C) {
    constexpr int CG = DOUT / 4;        // col groups of 4
    constexpr int THREADS = CG * 8;     // 8 row groups of 4 rows
    constexpr int BM = 32;
    __shared__ float As[BM * DIN];
    int tid = threadIdx.x;
    size_t r0 = (size_t)blockIdx.x * BM;
    const float4* Ag = (const float4*)(A + r0 * DIN);
    for (int i = tid; i < BM * DIN / 4; i += THREADS) ((float4*)As)[i] = Ag[i];
    __syncthreads();
    int tx = tid % CG, ty = tid / CG;
    float acc[4][4];
    #pragma unroll
    for (int i = 0; i < 4; i++)
        #pragma unroll
        for (int j = 0; j < 4; j++) acc[i][j] = 0.f;
    const float* Wp = W + tx * 4;
    #pragma unroll 4
    for (int k = 0; k < DIN; k++) {
        float4 b = *(const float4*)(Wp + (size_t)k * DOUT);
        float a0 = As[(ty * 4 + 0) * DIN + k];
        float a1 = As[(ty * 4 + 1) * DIN + k];
        float a2 = As[(ty * 4 + 2) * DIN + k];
        float a3 = As[(ty * 4 + 3) * DIN + k];
        acc[0][0] = fmaf(a0, b.x, acc[0][0]); acc[0][1] = fmaf(a0, b.y, acc[0][1]);
        acc[0][2] = fmaf(a0, b.z, acc[0][2]); acc[0][3] = fmaf(a0, b.w, acc[0][3]);
        acc[1][0] = fmaf(a1, b.x, acc[1][0]); acc[1][1] = fmaf(a1, b.y, acc[1][1]);
        acc[1][2] = fmaf(a1, b.z, acc[1][2]); acc[1][3] = fmaf(a1, b.w, acc[1][3]);
        acc[2][0] = fmaf(a2, b.x, acc[2][0]); acc[2][1] = fmaf(a2, b.y, acc[2][1]);
        acc[2][2] = fmaf(a2, b.z, acc[2][2]); acc[2][3] = fmaf(a2, b.w, acc[2][3]);
        acc[3][0] = fmaf(a3, b.x, acc[3][0]); acc[3][1] = fmaf(a3, b.y, acc[3][1]);
        acc[3][2] = fmaf(a3, b.z, acc[3][2]); acc[3][3] = fmaf(a3, b.w, acc[3][3]);
    }
    #pragma unroll
    for (int i = 0; i < 4; i++) {
        float4 r = make_float4(acc[i][0], acc[i][1], acc[i][2], acc[i][3]);
        if (BIASRELU) {
            float4 bb = *(const float4*)(bias + tx * 4);
            r.x = fmaxf(r.x + bb.x, 0.f); r.y = fmaxf(r.y + bb.y, 0.f);
            r.z = fmaxf(r.z + bb.z, 0.f); r.w = fmaxf(r.w + bb.w, 0.f);
        }
        *(float4*)(C + (r0 + ty * 4 + i) * DOUT + tx * 4) = r;
    }
}

// ---------------- aggregation: warp per node, gather over CSR ----------------
__global__ void aggregate_kernel(const float* __restrict__ h,
                                 const float* __restrict__ bias,
                                 float* __restrict__ outb) {
    int node = blockIdx.x * 8 + (threadIdx.x >> 5);
    if (node >= NNODES) return;
    int lane = threadIdx.x & 31;
    float di = g_dinv[node];
    float4 acc = ((const float4*)(h + (size_t)node * DH))[lane];
    float sc = di * di;
    acc.x *= sc; acc.y *= sc; acc.z *= sc; acc.w *= sc;
    int e0 = g_rowstart[node], e1 = g_rowstart[node + 1];
    for (int i = e0; i < e1; i++) {
        int c = __ldg(&g_col[i]);
        float w = __ldg(&g_wgt[i]);
        float4 v = ((const float4*)(h + (size_t)c * DH))[lane];
        acc.x = fmaf(v.x, w, acc.x); acc.y = fmaf(v.y, w, acc.y);
        acc.z = fmaf(v.z, w, acc.z); acc.w = fmaf(v.w, w, acc.w);
    }
    float4 b = ((const float4*)bias)[lane];
    acc.x += b.x; acc.y += b.y; acc.z += b.z; acc.w += b.w;
    ((float4*)(outb + (size_t)node * DH))[lane] = acc;
}

// ---------------- BatchNorm ----------------
__global__ void colstats_kernel(const float* __restrict__ a,
                                float* __restrict__ sum, float* __restrict__ sq) {
    int c = threadIdx.x;  // 128 threads
    float s = 0.f, q = 0.f;
    for (int r = blockIdx.x; r < NNODES; r += gridDim.x) {
        float v = a[(size_t)r * DH + c];
        s += v; q += v * v;
    }
    atomicAdd(&sum[c], s);
    atomicAdd(&sq[c], q);
}

__global__ void bn_finalize_kernel(const float* __restrict__ sum, const float* __restrict__ sq,
                                   const float* __restrict__ g, const float* __restrict__ be) {
    int c = threadIdx.x;  // 128
    float m = sum[c] * (1.0f / NNODES);
    float var = sq[c] * (1.0f / NNODES) - m * m;
    float inv = rsqrtf(var + BN_EPS);
    float scl = g[c] * inv;
    g_scale[c] = scl;
    g_shift[c] = fmaf(-m, scl, be[c]);
}

__global__ void bn_relu_kernel(float4* __restrict__ buf) {
    size_t i = (size_t)blockIdx.x * blockDim.x + threadIdx.x;
    if (i >= (size_t)NNODES * (DH / 4)) return;
    int c = (int)(i & (DH / 4 - 1));
    float4 v = buf[i];
    float4 sc = ((const float4*)g_scale)[c];
    float4 sh = ((const float4*)g_shift)[c];
    v.x = fmaxf(fmaf(v.x, sc.x, sh.x), 0.f);
    v.y = fmaxf(fmaf(v.y, sc.y, sh.y), 0.f);
    v.z = fmaxf(fmaf(v.z, sc.z, sh.z), 0.f);
    v.w = fmaxf(fmaf(v.w, sc.w, sh.w), 0.f);
    buf[i] = v;
}

// ---------------- head layer 2: dot(64) + sigmoid ----------------
__global__ void head2_kernel(const float* __restrict__ h, const float* __restrict__ Wh2,
                             const float* __restrict__ bh2, float* __restrict__ out) {
    int r = blockIdx.x * 256 + threadIdx.x;
    if (r >= NNODES) return;
    const float4* hp = (const float4*)(h + (size_t)r * 64);
    float acc = bh2[0];
    #pragma unroll
    for (int i = 0; i < 16; i++) {
        float4 v = hp[i];
        float4 w = __ldg(((const float4*)Wh2) + i);
        acc += v.x * w.x + v.y * w.y + v.z * w.z + v.w * w.w;
    }
    out[r] = 1.0f / (1.0f + __expf(-acc));
}

// ---------------- launch ----------------
extern "C" void kernel_launch(void* const* d_in, const int* in_sizes, int n_in,
                              void* d_out, int out_size) {
    const float* x  = (const float*)d_in[0];
    const void*  ei = d_in[1];
    const float* W1 = (const float*)d_in[2];
    const float* b1 = (const float*)d_in[3];
    const float* g1 = (const float*)d_in[4];
    const float* be1 = (const float*)d_in[5];
    const float* W2 = (const float*)d_in[6];
    const float* b2 = (const float*)d_in[7];
    const float* g2 = (const float*)d_in[8];
    const float* be2 = (const float*)d_in[9];
    const float* Wh1 = (const float*)d_in[10];
    const float* bh1 = (const float*)d_in[11];
    const float* Wh2 = (const float*)d_in[12];
    const float* bh2 = (const float*)d_in[13];
    float* out = (float*)d_out;

    float *bufA, *bufB, *sum1, *sq1, *sum2, *sq2;
    cudaGetSymbolAddress((void**)&bufA, g_bufA);
    cudaGetSymbolAddress((void**)&bufB, g_bufB);
    cudaGetSymbolAddress((void**)&sum1, g_sum1);
    cudaGetSymbolAddress((void**)&sq1, g_sq1);
    cudaGetSymbolAddress((void**)&sum2, g_sum2);
    cudaGetSymbolAddress((void**)&sq2, g_sq2);

    const int NB = (NNODES + 1023) / 1024;  // 98

    // graph prep (CSR build, shared by both conv layers)
    detect_kernel<<<1, 1>>>(ei);
    zero_kernel<<<(NNODES + 255) / 256, 256>>>();
    hist_kernel<<<(NEDGES + 255) / 256, 256>>>(ei);
    dinv_kernel<<<(NNODES + 255) / 256, 256>>>();
    scanA_kernel<<<NB, 1024>>>();
    scanB_kernel<<<1, 128>>>(NB);
    scanC_kernel<<<NB, 1024>>>();
    fill_kernel<<<(NEDGES + 255) / 256, 256>>>(ei);

    // layer 1
    gemm_kernel<64, 128, false><<<NNODES / 32, 256>>>(x, W1, nullptr, bufA);
    aggregate_kernel<<<(NNODES + 7) / 8, 256>>>(bufA, b1, bufB);
    colstats_kernel<<<1024, 128>>>(bufB, sum1, sq1);
    bn_finalize_kernel<<<1, 128>>>(sum1, sq1, g1, be1);
    bn_relu_kernel<<<(NNODES * (DH / 4) + 255) / 256, 256>>>((float4*)bufB);

    // layer 2
    gemm_kernel<128, 128, false><<<NNODES / 32, 256>>>(bufB, W2, nullptr, bufA);
    aggregate_kernel<<<(NNODES + 7) / 8, 256>>>(bufA, b2, bufB);
    colstats_kernel<<<1024, 128>>>(bufB, sum2, sq2);
    bn_finalize_kernel<<<1, 128>>>(sum2, sq2, g2, be2);
    bn_relu_kernel<<<(NNODES * (DH / 4) + 255) / 256, 256>>>((float4*)bufB);

    // head
    gemm_kernel<128, 64, true><<<NNODES / 32, 128>>>(bufB, Wh1, bh1, bufA);
    head2_kernel<<<(NNODES + 255) / 256, 256>>>(bufA, Wh2, bh2, out);
}

// round 4
// speedup vs baseline: 1.1689x; 1.1689x over previous
#include <cuda_runtime.h>
#include <math.h>

#define NNODES 100000
#define NEDGES 1600000
#define DH 128
#define BN_EPS 1e-5f

typedef unsigned long long u64;

// ---------------- f32x2 packed-FMA helpers (sm_100+) ----------------
__device__ __forceinline__ u64 pack2(float x) {
    u64 r; unsigned u = __float_as_uint(x);
    asm("mov.b64 %0, {%1, %1};" : "=l"(r) : "r"(u));
    return r;
}
__device__ __forceinline__ u64 packf2(float lo, float hi) {
    u64 r;
    asm("mov.b64 %0, {%1, %2};" : "=l"(r)
        : "r"(__float_as_uint(lo)), "r"(__float_as_uint(hi)));
    return r;
}
__device__ __forceinline__ float2 unpack2(u64 v) {
    unsigned lo, hi;
    asm("mov.b64 {%0, %1}, %2;" : "=r"(lo), "=r"(hi) : "l"(v));
    return make_float2(__uint_as_float(lo), __uint_as_float(hi));
}
__device__ __forceinline__ void fma2(u64& d, u64 a, u64 b) {
    asm("fma.rn.f32x2 %0, %1, %2, %0;" : "+l"(d) : "l"(a), "l"(b));
}

// ---------------- scratch (static __device__, no allocs) ----------------
__device__ __align__(16) float g_bufA[(size_t)NNODES * DH];
__device__ __align__(16) float g_bufB[(size_t)NNODES * DH];
__device__ int   g_count[NNODES];
__device__ float g_dinv[NNODES];
__device__ int   g_rowstart[NNODES + 1];
__device__ int   g_cursor[NNODES];
__device__ int   g_col[NEDGES];
__device__ float g_wgt[NEDGES];
__device__ float g_sum1[DH], g_sq1[DH], g_sum2[DH], g_sq2[DH];
__device__ __align__(16) float g_scale1[DH], g_shift1[DH];
__device__ __align__(16) float g_scale2[DH], g_shift2[DH];
__device__ int   g_psum[128];
__device__ int   g_is64;

__device__ __forceinline__ int load_idx(const void* ei, long long pos, int is64) {
    return is64 ? (int)((const long long*)ei)[pos] : ((const int*)ei)[pos];
}

// ---------------- utility: block exclusive scan (shfl-based) ----------------
__device__ __forceinline__ int block_excl_scan(int v) {
    const unsigned full = 0xffffffffu;
    int tid = threadIdx.x, lane = tid & 31, wid = tid >> 5;
    int incl = v;
    #pragma unroll
    for (int o = 1; o < 32; o <<= 1) {
        int t = __shfl_up_sync(full, incl, o);
        if (lane >= o) incl += t;
    }
    __shared__ int ws[32];
    if (lane == 31) ws[wid] = incl;
    __syncthreads();
    if (wid == 0) {
        int nw = blockDim.x >> 5;
        int s = (lane < nw) ? ws[lane] : 0;
        #pragma unroll
        for (int o = 1; o < 32; o <<= 1) {
            int t = __shfl_up_sync(full, s, o);
            if (lane >= o) s += t;
        }
        ws[lane] = s;
    }
    __syncthreads();
    int base = wid ? ws[wid - 1] : 0;
    return base + incl - v;
}

// ---------------- graph prep ----------------
__global__ void zero_detect_kernel(const void* ei) {
    int i = blockIdx.x * 256 + threadIdx.x;
    if (i < NNODES) g_count[i] = 0;
    if (i < DH) { g_sum1[i] = 0.f; g_sq1[i] = 0.f; g_sum2[i] = 0.f; g_sq2[i] = 0.f; }
    if (i == 0) {
        // int64 vs int32 transport detection: genuine int64 indices all < NNODES
        const long long* p = (const long long*)ei;
        int ok = 1;
        #pragma unroll
        for (int j = 0; j < 8; j++) {
            long long v = p[j];
            if (v < 0 || v >= NNODES) ok = 0;
        }
        g_is64 = ok;
    }
}

__global__ void hist_kernel(const void* __restrict__ ei) {
    int e = blockIdx.x * 256 + threadIdx.x;
    int is64 = g_is64;
    if (e < NEDGES) {
        int d = load_idx(ei, (long long)NEDGES + e, is64);
        atomicAdd(&g_count[d], 1);
    }
}

// scanA also computes dinv (both read g_count)
__global__ void scanA_kernel() {
    int i = blockIdx.x * 1024 + threadIdx.x;
    int v = (i < NNODES) ? g_count[i] : 0;
    if (i < NNODES) g_dinv[i] = rsqrtf((float)v + 1.0f);
    const unsigned full = 0xffffffffu;
    int s = v;
    #pragma unroll
    for (int o = 16; o; o >>= 1) s += __shfl_down_sync(full, s, o);
    __shared__ int ws[32];
    int lane = threadIdx.x & 31, wid = threadIdx.x >> 5;
    if (lane == 0) ws[wid] = s;
    __syncthreads();
    if (wid == 0) {
        int t = ws[lane];
        #pragma unroll
        for (int o = 16; o; o >>= 1) t += __shfl_down_sync(full, t, o);
        if (lane == 0) g_psum[blockIdx.x] = t;
    }
}

__global__ void scanB_kernel(int nb) {
    int tid = threadIdx.x;
    int v = (tid < nb) ? g_psum[tid] : 0;
    int ex = block_excl_scan(v);
    __syncthreads();
    if (tid < nb) g_psum[tid] = ex;
}

__global__ void scanC_kernel() {
    int i = blockIdx.x * 1024 + threadIdx.x;
    int v = (i < NNODES) ? g_count[i] : 0;
    int ex = block_excl_scan(v) + g_psum[blockIdx.x];
    if (i < NNODES) { g_rowstart[i] = ex; g_cursor[i] = ex; }
    if (i == NNODES - 1) g_rowstart[NNODES] = ex + v;
}

__global__ void fill_kernel(const void* __restrict__ ei) {
    int e = blockIdx.x * 256 + threadIdx.x;
    int is64 = g_is64;
    if (e < NEDGES) {
        int s = load_idx(ei, e, is64);
        int d = load_idx(ei, (long long)NEDGES + e, is64);
        int pos = atomicAdd(&g_cursor[d], 1);
        g_col[pos] = s;
        g_wgt[pos] = g_dinv[s] * g_dinv[d];
    }
}

// ---------------- GEMM: C[N,DOUT] = bnrelu?(A)[N,DIN] @ W[DIN,DOUT] ----------------
// f32x2 packed accumulators; optional fused BN(scale,shift)+ReLU on A load.
template <int DIN, int DOUT, bool BNIN>
__global__ void gemm_kernel(const float* __restrict__ A, const float* __restrict__ W,
                            float* __restrict__ C,
                            const float* __restrict__ scale, const float* __restrict__ shift) {
    constexpr int CG = DOUT / 4;
    constexpr int THREADS = CG * 8;
    constexpr int BM = 32;
    __shared__ float As[BM * DIN];
    int tid = threadIdx.x;
    size_t r0 = (size_t)blockIdx.x * BM;
    const float4* Ag = (const float4*)(A + r0 * DIN);
    #pragma unroll
    for (int i = tid; i < BM * DIN / 4; i += THREADS) {
        float4 v = Ag[i];
        if (BNIN) {
            int c4 = i & (DIN / 4 - 1);
            float4 sc = ((const float4*)scale)[c4];
            float4 sh = ((const float4*)shift)[c4];
            v.x = fmaxf(fmaf(v.x, sc.x, sh.x), 0.f);
            v.y = fmaxf(fmaf(v.y, sc.y, sh.y), 0.f);
            v.z = fmaxf(fmaf(v.z, sc.z, sh.z), 0.f);
            v.w = fmaxf(fmaf(v.w, sc.w, sh.w), 0.f);
        }
        ((float4*)As)[i] = v;
    }
    __syncthreads();
    int tx = tid % CG, ty = tid / CG;
    u64 acc2[4][2];
    #pragma unroll
    for (int i = 0; i < 4; i++) { acc2[i][0] = 0ull; acc2[i][1] = 0ull; }
    const float* Wp = W + tx * 4;
    #pragma unroll 4
    for (int k = 0; k < DIN; k++) {
        ulonglong2 bv = *(const ulonglong2*)(Wp + (size_t)k * DOUT);
        #pragma unroll
        for (int i = 0; i < 4; i++) {
            u64 aa = pack2(As[(ty * 4 + i) * DIN + k]);
            fma2(acc2[i][0], aa, bv.x);
            fma2(acc2[i][1], aa, bv.y);
        }
    }
    #pragma unroll
    for (int i = 0; i < 4; i++) {
        float2 c01 = unpack2(acc2[i][0]);
        float2 c23 = unpack2(acc2[i][1]);
        *(float4*)(C + (r0 + ty * 4 + i) * DOUT + tx * 4) =
            make_float4(c01.x, c01.y, c23.x, c23.y);
    }
}

// ---------------- aggregation: warp per node + fused column stats ----------------
// 512 threads = 16 warps = 16 nodes/block; NNODES/16 = 6250 exact.
__global__ void aggregate_kernel(const float* __restrict__ h,
                                 const float* __restrict__ bias,
                                 float* __restrict__ outb,
                                 float* __restrict__ sum, float* __restrict__ sq) {
    __shared__ float s_sum[16][DH];
    __shared__ float s_sq[16][DH];
    int tid = threadIdx.x;
    int w = tid >> 5, lane = tid & 31;
    int node = blockIdx.x * 16 + w;
    float di = g_dinv[node];
    float4 self = ((const float4*)(h + (size_t)node * DH))[lane];
    float s2 = di * di;
    u64 a01 = packf2(self.x * s2, self.y * s2);
    u64 a23 = packf2(self.z * s2, self.w * s2);
    int e0 = g_rowstart[node], e1 = g_rowstart[node + 1];
    for (int i = e0; i < e1; i++) {
        int c = __ldg(&g_col[i]);
        u64 ww = pack2(__ldg(&g_wgt[i]));
        ulonglong2 vv = ((const ulonglong2*)(h + (size_t)c * DH))[lane];
        fma2(a01, vv.x, ww);
        fma2(a23, vv.y, ww);
    }
    float2 c01 = unpack2(a01), c23 = unpack2(a23);
    float4 b = ((const float4*)bias)[lane];
    float4 r = make_float4(c01.x + b.x, c01.y + b.y, c23.x + b.z, c23.y + b.w);
    ((float4*)(outb + (size_t)node * DH))[lane] = r;
    // per-warp stats partials (each lane owns 4 distinct channels)
    *(float4*)&s_sum[w][lane * 4] = r;
    *(float4*)&s_sq[w][lane * 4] =
        make_float4(r.x * r.x, r.y * r.y, r.z * r.z, r.w * r.w);
    __syncthreads();
    if (tid < DH) {
        float a = 0.f, bq = 0.f;
        #pragma unroll
        for (int ww2 = 0; ww2 < 16; ww2++) { a += s_sum[ww2][tid]; bq += s_sq[ww2][tid]; }
        atomicAdd(&sum[tid], a);
        atomicAdd(&sq[tid], bq);
    }
}

// ---------------- BatchNorm finalize ----------------
__global__ void bn_finalize_kernel(const float* __restrict__ sum, const float* __restrict__ sq,
                                   const float* __restrict__ g, const float* __restrict__ be,
                                   float* __restrict__ scale, float* __restrict__ shift) {
    int c = threadIdx.x;  // 128
    float m = sum[c] * (1.0f / NNODES);
    float var = sq[c] * (1.0f / NNODES) - m * m;
    float inv = rsqrtf(var + BN_EPS);
    float scl = g[c] * inv;
    scale[c] = scl;
    shift[c] = fmaf(-m, scl, be[c]);
}

// ---------------- fused head: BN2+ReLU -> Linear(128,64)+ReLU -> dot(64)+sigmoid ----------------
__global__ void head_kernel(const float* __restrict__ A, const float* __restrict__ Wh1,
                            const float* __restrict__ bh1, const float* __restrict__ Wh2,
                            const float* __restrict__ bh2,
                            const float* __restrict__ scale, const float* __restrict__ shift,
                            float* __restrict__ out) {
    constexpr int DIN = 128, DOUT = 64, CG = 16, THREADS = 128, BM = 32;
    __shared__ float As[BM * DIN];
    int tid = threadIdx.x;
    size_t r0 = (size_t)blockIdx.x * BM;
    const float4* Ag = (const float4*)(A + r0 * DIN);
    #pragma unroll
    for (int i = tid; i < BM * DIN / 4; i += THREADS) {
        float4 v = Ag[i];
        int c4 = i & (DIN / 4 - 1);
        float4 sc = ((const float4*)scale)[c4];
        float4 sh = ((const float4*)shift)[c4];
        v.x = fmaxf(fmaf(v.x, sc.x, sh.x), 0.f);
        v.y = fmaxf(fmaf(v.y, sc.y, sh.y), 0.f);
        v.z = fmaxf(fmaf(v.z, sc.z, sh.z), 0.f);
        v.w = fmaxf(fmaf(v.w, sc.w, sh.w), 0.f);
        ((float4*)As)[i] = v;
    }
    __syncthreads();
    int tx = tid % CG, ty = tid / CG;
    u64 acc2[4][2];
    #pragma unroll
    for (int i = 0; i < 4; i++) { acc2[i][0] = 0ull; acc2[i][1] = 0ull; }
    const float* Wp = Wh1 + tx * 4;
    #pragma unroll 4
    for (int k = 0; k < DIN; k++) {
        ulonglong2 bv = *(const ulonglong2*)(Wp + (size_t)k * DOUT);
        #pragma unroll
        for (int i = 0; i < 4; i++) {
            u64 aa = pack2(As[(ty * 4 + i) * DIN + k]);
            fma2(acc2[i][0], aa, bv.x);
            fma2(acc2[i][1], aa, bv.y);
        }
    }
    const unsigned full = 0xffffffffu;
    float4 bb = ((const float4*)bh1)[tx];
    float4 w2 = ((const float4*)Wh2)[tx];
    float b2v = bh2[0];
    #pragma unroll
    for (int i = 0; i < 4; i++) {
        float2 c01 = unpack2(acc2[i][0]);
        float2 c23 = unpack2(acc2[i][1]);
        float h0 = fmaxf(c01.x + bb.x, 0.f);
        float h1 = fmaxf(c01.y + bb.y, 0.f);
        float h2 = fmaxf(c23.x + bb.z, 0.f);
        float h3 = fmaxf(c23.y + bb.w, 0.f);
        float p = h0 * w2.x + h1 * w2.y + h2 * w2.z + h3 * w2.w;
        p += __shfl_down_sync(full, p, 8, 16);
        p += __shfl_down_sync(full, p, 4, 16);
        p += __shfl_down_sync(full, p, 2, 16);
        p += __shfl_down_sync(full, p, 1, 16);
        if (tx == 0) out[r0 + ty * 4 + i] = 1.0f / (1.0f + __expf(-(p + b2v)));
    }
}

// ---------------- launch ----------------
extern "C" void kernel_launch(void* const* d_in, const int* in_sizes, int n_in,
                              void* d_out, int out_size) {
    const float* x  = (const float*)d_in[0];
    const void*  ei = d_in[1];
    const float* W1 = (const float*)d_in[2];
    const float* b1 = (const float*)d_in[3];
    const float* g1 = (const float*)d_in[4];
    const float* be1 = (const float*)d_in[5];
    const float* W2 = (const float*)d_in[6];
    const float* b2 = (const float*)d_in[7];
    const float* g2 = (const float*)d_in[8];
    const float* be2 = (const float*)d_in[9];
    const float* Wh1 = (const float*)d_in[10];
    const float* bh1 = (const float*)d_in[11];
    const float* Wh2 = (const float*)d_in[12];
    const float* bh2 = (const float*)d_in[13];
    float* out = (float*)d_out;

    float *bufA, *bufB, *sum1, *sq1, *sum2, *sq2, *sc1, *sh1, *sc2, *sh2;
    cudaGetSymbolAddress((void**)&bufA, g_bufA);
    cudaGetSymbolAddress((void**)&bufB, g_bufB);
    cudaGetSymbolAddress((void**)&sum1, g_sum1);
    cudaGetSymbolAddress((void**)&sq1, g_sq1);
    cudaGetSymbolAddress((void**)&sum2, g_sum2);
    cudaGetSymbolAddress((void**)&sq2, g_sq2);
    cudaGetSymbolAddress((void**)&sc1, g_scale1);
    cudaGetSymbolAddress((void**)&sh1, g_shift1);
    cudaGetSymbolAddress((void**)&sc2, g_scale2);
    cudaGetSymbolAddress((void**)&sh2, g_shift2);

    const int NB = (NNODES + 1023) / 1024;  // 98

    // graph prep (CSR build, shared by both conv layers)
    zero_detect_kernel<<<(NNODES + 255) / 256, 256>>>(ei);
    hist_kernel<<<(NEDGES + 255) / 256, 256>>>(ei);
    scanA_kernel<<<NB, 1024>>>();
    scanB_kernel<<<1, 128>>>(NB);
    scanC_kernel<<<NB, 1024>>>();
    fill_kernel<<<(NEDGES + 255) / 256, 256>>>(ei);

    // layer 1
    gemm_kernel<64, 128, false><<<NNODES / 32, 256>>>(x, W1, bufA, nullptr, nullptr);
    aggregate_kernel<<<NNODES / 16, 512>>>(bufA, b1, bufB, sum1, sq1);
    bn_finalize_kernel<<<1, 128>>>(sum1, sq1, g1, be1, sc1, sh1);

    // layer 2 (BN1+ReLU fused into A-load)
    gemm_kernel<128, 128, true><<<NNODES / 32, 256>>>(bufB, W2, bufA, sc1, sh1);
    aggregate_kernel<<<NNODES / 16, 512>>>(bufA, b2, bufB, sum2, sq2);
    bn_finalize_kernel<<<1, 128>>>(sum2, sq2, g2, be2, sc2, sh2);

    // head (BN2+ReLU + Linear+ReLU + dot + sigmoid fused)
    head_kernel<<<NNODES / 32, 128>>>(bufB, Wh1, bh1, Wh2, bh2, sc2, sh2, out);
}

// round 5
// speedup vs baseline: 1.3072x; 1.1183x over previous
#include <cuda_runtime.h>
#include <cuda_fp16.h>
#include <math.h>

#define NNODES 100000
#define NEDGES 1600000
#define DH 128
#define BN_EPS 1e-5f

typedef unsigned long long u64;

// ---------------- f32x2 packed-FMA helpers (sm_100+) ----------------
__device__ __forceinline__ u64 pack2(float x) {
    u64 r; unsigned u = __float_as_uint(x);
    asm("mov.b64 %0, {%1, %1};" : "=l"(r) : "r"(u));
    return r;
}
__device__ __forceinline__ float2 unpack2(u64 v) {
    unsigned lo, hi;
    asm("mov.b64 {%0, %1}, %2;" : "=r"(lo), "=r"(hi) : "l"(v));
    return make_float2(__uint_as_float(lo), __uint_as_float(hi));
}
__device__ __forceinline__ void fma2(u64& d, u64 a, u64 b) {
    asm("fma.rn.f32x2 %0, %1, %2, %0;" : "+l"(d) : "l"(a), "l"(b));
}

// ---------------- scratch (static __device__, no allocs) ----------------
__device__ __align__(16) __half g_bufH[(size_t)NNODES * DH];  // fp16 gather operand
__device__ __align__(16) float g_bufB[(size_t)NNODES * DH];   // fp32 aggregate output
__device__ int   g_count[NNODES];
__device__ float g_dinv[NNODES];
__device__ int   g_rowstart[NNODES + 1];
__device__ int   g_cursor[NNODES];
__device__ int   g_col[NEDGES];
__device__ float g_wgt[NEDGES];
__device__ float g_sum1[DH], g_sq1[DH], g_sum2[DH], g_sq2[DH];
__device__ __align__(16) float g_scale1[DH], g_shift1[DH];
__device__ __align__(16) float g_scale2[DH], g_shift2[DH];
__device__ int   g_psum[128];
__device__ int   g_is64;

__device__ __forceinline__ int load_idx(const void* ei, long long pos, int is64) {
    return is64 ? (int)((const long long*)ei)[pos] : ((const int*)ei)[pos];
}

// ---------------- utility: block exclusive scan (shfl-based) ----------------
__device__ __forceinline__ int block_excl_scan(int v) {
    const unsigned full = 0xffffffffu;
    int tid = threadIdx.x, lane = tid & 31, wid = tid >> 5;
    int incl = v;
    #pragma unroll
    for (int o = 1; o < 32; o <<= 1) {
        int t = __shfl_up_sync(full, incl, o);
        if (lane >= o) incl += t;
    }
    __shared__ int ws[32];
    if (lane == 31) ws[wid] = incl;
    __syncthreads();
    if (wid == 0) {
        int nw = blockDim.x >> 5;
        int s = (lane < nw) ? ws[lane] : 0;
        #pragma unroll
        for (int o = 1; o < 32; o <<= 1) {
            int t = __shfl_up_sync(full, s, o);
            if (lane >= o) s += t;
        }
        ws[lane] = s;
    }
    __syncthreads();
    int base = wid ? ws[wid - 1] : 0;
    return base + incl - v;
}

// ---------------- graph prep ----------------
__global__ void zero_detect_kernel(const void* ei) {
    int i = blockIdx.x * 256 + threadIdx.x;
    if (i < NNODES) g_count[i] = 0;
    if (i < DH) { g_sum1[i] = 0.f; g_sq1[i] = 0.f; g_sum2[i] = 0.f; g_sq2[i] = 0.f; }
    if (i == 0) {
        // int64 vs int32 transport detection: genuine int64 indices all < NNODES
        const long long* p = (const long long*)ei;
        int ok = 1;
        #pragma unroll
        for (int j = 0; j < 8; j++) {
            long long v = p[j];
            if (v < 0 || v >= NNODES) ok = 0;
        }
        g_is64 = ok;
    }
}

__global__ void hist_kernel(const void* __restrict__ ei) {
    int e = blockIdx.x * 256 + threadIdx.x;
    int is64 = g_is64;
    if (e < NEDGES) {
        int d = load_idx(ei, (long long)NEDGES + e, is64);
        atomicAdd(&g_count[d], 1);
    }
}

// scanA also computes dinv (both read g_count)
__global__ void scanA_kernel() {
    int i = blockIdx.x * 1024 + threadIdx.x;
    int v = (i < NNODES) ? g_count[i] : 0;
    if (i < NNODES) g_dinv[i] = rsqrtf((float)v + 1.0f);
    const unsigned full = 0xffffffffu;
    int s = v;
    #pragma unroll
    for (int o = 16; o; o >>= 1) s += __shfl_down_sync(full, s, o);
    __shared__ int ws[32];
    int lane = threadIdx.x & 31, wid = threadIdx.x >> 5;
    if (lane == 0) ws[wid] = s;
    __syncthreads();
    if (wid == 0) {
        int t = ws[lane];
        #pragma unroll
        for (int o = 16; o; o >>= 1) t += __shfl_down_sync(full, t, o);
        if (lane == 0) g_psum[blockIdx.x] = t;
    }
}

__global__ void scanB_kernel(int nb) {
    int tid = threadIdx.x;
    int v = (tid < nb) ? g_psum[tid] : 0;
    int ex = block_excl_scan(v);
    __syncthreads();
    if (tid < nb) g_psum[tid] = ex;
}

__global__ void scanC_kernel() {
    int i = blockIdx.x * 1024 + threadIdx.x;
    int v = (i < NNODES) ? g_count[i] : 0;
    int ex = block_excl_scan(v) + g_psum[blockIdx.x];
    if (i < NNODES) { g_rowstart[i] = ex; g_cursor[i] = ex; }
    if (i == NNODES - 1) g_rowstart[NNODES] = ex + v;
}

__global__ void fill_kernel(const void* __restrict__ ei) {
    int e = blockIdx.x * 256 + threadIdx.x;
    int is64 = g_is64;
    if (e < NEDGES) {
        int s = load_idx(ei, e, is64);
        int d = load_idx(ei, (long long)NEDGES + e, is64);
        int pos = atomicAdd(&g_cursor[d], 1);
        g_col[pos] = s;
        g_wgt[pos] = g_dinv[s] * g_dinv[d];
    }
}

// ---------------- GEMM: H[N,DOUT](fp16) = bnrelu?(A)[N,DIN] @ W[DIN,DOUT] ----------------
// f32x2 packed accumulators; optional fused BN(scale,shift)+ReLU on A load; fp16 output.
template <int DIN, int DOUT, bool BNIN>
__global__ void gemm_kernel(const float* __restrict__ A, const float* __restrict__ W,
                            __half* __restrict__ C,
                            const float* __restrict__ scale, const float* __restrict__ shift) {
    constexpr int CG = DOUT / 4;
    constexpr int THREADS = CG * 8;
    constexpr int BM = 32;
    __shared__ float As[BM * DIN];
    int tid = threadIdx.x;
    size_t r0 = (size_t)blockIdx.x * BM;
    const float4* Ag = (const float4*)(A + r0 * DIN);
    #pragma unroll
    for (int i = tid; i < BM * DIN / 4; i += THREADS) {
        float4 v = Ag[i];
        if (BNIN) {
            int c4 = i & (DIN / 4 - 1);
            float4 sc = ((const float4*)scale)[c4];
            float4 sh = ((const float4*)shift)[c4];
            v.x = fmaxf(fmaf(v.x, sc.x, sh.x), 0.f);
            v.y = fmaxf(fmaf(v.y, sc.y, sh.y), 0.f);
            v.z = fmaxf(fmaf(v.z, sc.z, sh.z), 0.f);
            v.w = fmaxf(fmaf(v.w, sc.w, sh.w), 0.f);
        }
        ((float4*)As)[i] = v;
    }
    __syncthreads();
    int tx = tid % CG, ty = tid / CG;
    u64 acc2[4][2];
    #pragma unroll
    for (int i = 0; i < 4; i++) { acc2[i][0] = 0ull; acc2[i][1] = 0ull; }
    const float* Wp = W + tx * 4;
    #pragma unroll 4
    for (int k = 0; k < DIN; k++) {
        ulonglong2 bv = *(const ulonglong2*)(Wp + (size_t)k * DOUT);
        #pragma unroll
        for (int i = 0; i < 4; i++) {
            u64 aa = pack2(As[(ty * 4 + i) * DIN + k]);
            fma2(acc2[i][0], aa, bv.x);
            fma2(acc2[i][1], aa, bv.y);
        }
    }
    #pragma unroll
    for (int i = 0; i < 4; i++) {
        float2 c01 = unpack2(acc2[i][0]);
        float2 c23 = unpack2(acc2[i][1]);
        __half2 h01 = __floats2half2_rn(c01.x, c01.y);
        __half2 h23 = __floats2half2_rn(c23.x, c23.y);
        uint2 packed = make_uint2(*(unsigned*)&h01, *(unsigned*)&h23);
        *(uint2*)(C + (r0 + ty * 4 + i) * DOUT + tx * 4) = packed;
    }
}

// ---------------- aggregation: warp per node, fp16 gather, fp32 accumulate ----------------
// 512 threads = 16 warps = 16 nodes/block; NNODES/16 = 6250 exact.
__global__ void aggregate_kernel(const __half* __restrict__ h,
                                 const float* __restrict__ bias,
                                 float* __restrict__ outb,
                                 float* __restrict__ sum, float* __restrict__ sq) {
    __shared__ float s_sum[16][DH];
    __shared__ float s_sq[16][DH];
    int tid = threadIdx.x;
    int w = tid >> 5, lane = tid & 31;
    int node = blockIdx.x * 16 + w;
    float di = g_dinv[node];
    float s2 = di * di;
    uint2 sv = ((const uint2*)(h + (size_t)node * DH))[lane];
    float2 f01 = __half22float2(*(__half2*)&sv.x);
    float2 f23 = __half22float2(*(__half2*)&sv.y);
    float a0 = f01.x * s2, a1 = f01.y * s2, a2 = f23.x * s2, a3 = f23.y * s2;
    int e0 = g_rowstart[node], e1 = g_rowstart[node + 1];
    for (int i = e0; i < e1; i++) {
        int c = __ldg(&g_col[i]);
        float ww = __ldg(&g_wgt[i]);
        uint2 vv = ((const uint2*)(h + (size_t)c * DH))[lane];
        float2 v01 = __half22float2(*(__half2*)&vv.x);
        float2 v23 = __half22float2(*(__half2*)&vv.y);
        a0 = fmaf(v01.x, ww, a0);
        a1 = fmaf(v01.y, ww, a1);
        a2 = fmaf(v23.x, ww, a2);
        a3 = fmaf(v23.y, ww, a3);
    }
    float4 b = ((const float4*)bias)[lane];
    float4 r = make_float4(a0 + b.x, a1 + b.y, a2 + b.z, a3 + b.w);
    ((float4*)(outb + (size_t)node * DH))[lane] = r;
    // per-warp stats partials (each lane owns 4 distinct channels)
    *(float4*)&s_sum[w][lane * 4] = r;
    *(float4*)&s_sq[w][lane * 4] =
        make_float4(r.x * r.x, r.y * r.y, r.z * r.z, r.w * r.w);
    __syncthreads();
    if (tid < DH) {
        float a = 0.f, bq = 0.f;
        #pragma unroll
        for (int ww2 = 0; ww2 < 16; ww2++) { a += s_sum[ww2][tid]; bq += s_sq[ww2][tid]; }
        atomicAdd(&sum[tid], a);
        atomicAdd(&sq[tid], bq);
    }
}

// ---------------- BatchNorm finalize ----------------
__global__ void bn_finalize_kernel(const float* __restrict__ sum, const float* __restrict__ sq,
                                   const float* __restrict__ g, const float* __restrict__ be,
                                   float* __restrict__ scale, float* __restrict__ shift) {
    int c = threadIdx.x;  // 128
    float m = sum[c] * (1.0f / NNODES);
    float var = sq[c] * (1.0f / NNODES) - m * m;
    float inv = rsqrtf(var + BN_EPS);
    float scl = g[c] * inv;
    scale[c] = scl;
    shift[c] = fmaf(-m, scl, be[c]);
}

// ---------------- fused head: BN2+ReLU -> Linear(128,64)+ReLU -> dot(64)+sigmoid ----------------
__global__ void head_kernel(const float* __restrict__ A, const float* __restrict__ Wh1,
                            const float* __restrict__ bh1, const float* __restrict__ Wh2,
                            const float* __restrict__ bh2,
                            const float* __restrict__ scale, const float* __restrict__ shift,
                            float* __restrict__ out) {
    constexpr int DIN = 128, DOUT = 64, CG = 16, THREADS = 128, BM = 32;
    __shared__ float As[BM * DIN];
    int tid = threadIdx.x;
    size_t r0 = (size_t)blockIdx.x * BM;
    const float4* Ag = (const float4*)(A + r0 * DIN);
    #pragma unroll
    for (int i = tid; i < BM * DIN / 4; i += THREADS) {
        float4 v = Ag[i];
        int c4 = i & (DIN / 4 - 1);
        float4 sc = ((const float4*)scale)[c4];
        float4 sh = ((const float4*)shift)[c4];
        v.x = fmaxf(fmaf(v.x, sc.x, sh.x), 0.f);
        v.y = fmaxf(fmaf(v.y, sc.y, sh.y), 0.f);
        v.z = fmaxf(fmaf(v.z, sc.z, sh.z), 0.f);
        v.w = fmaxf(fmaf(v.w, sc.w, sh.w), 0.f);
        ((float4*)As)[i] = v;
    }
    __syncthreads();
    int tx = tid % CG, ty = tid / CG;
    u64 acc2[4][2];
    #pragma unroll
    for (int i = 0; i < 4; i++) { acc2[i][0] = 0ull; acc2[i][1] = 0ull; }
    const float* Wp = Wh1 + tx * 4;
    #pragma unroll 4
    for (int k = 0; k < DIN; k++) {
        ulonglong2 bv = *(const ulonglong2*)(Wp + (size_t)k * DOUT);
        #pragma unroll
        for (int i = 0; i < 4; i++) {
            u64 aa = pack2(As[(ty * 4 + i) * DIN + k]);
            fma2(acc2[i][0], aa, bv.x);
            fma2(acc2[i][1], aa, bv.y);
        }
    }
    const unsigned full = 0xffffffffu;
    float4 bb = ((const float4*)bh1)[tx];
    float4 w2 = ((const float4*)Wh2)[tx];
    float b2v = bh2[0];
    #pragma unroll
    for (int i = 0; i < 4; i++) {
        float2 c01 = unpack2(acc2[i][0]);
        float2 c23 = unpack2(acc2[i][1]);
        float h0 = fmaxf(c01.x + bb.x, 0.f);
        float h1 = fmaxf(c01.y + bb.y, 0.f);
        float h2 = fmaxf(c23.x + bb.z, 0.f);
        float h3 = fmaxf(c23.y + bb.w, 0.f);
        float p = h0 * w2.x + h1 * w2.y + h2 * w2.z + h3 * w2.w;
        p += __shfl_down_sync(full, p, 8, 16);
        p += __shfl_down_sync(full, p, 4, 16);
        p += __shfl_down_sync(full, p, 2, 16);
        p += __shfl_down_sync(full, p, 1, 16);
        if (tx == 0) out[r0 + ty * 4 + i] = 1.0f / (1.0f + __expf(-(p + b2v)));
    }
}

// ---------------- launch ----------------
extern "C" void kernel_launch(void* const* d_in, const int* in_sizes, int n_in,
                              void* d_out, int out_size) {
    const float* x  = (const float*)d_in[0];
    const void*  ei = d_in[1];
    const float* W1 = (const float*)d_in[2];
    const float* b1 = (const float*)d_in[3];
    const float* g1 = (const float*)d_in[4];
    const float* be1 = (const float*)d_in[5];
    const float* W2 = (const float*)d_in[6];
    const float* b2 = (const float*)d_in[7];
    const float* g2 = (const float*)d_in[8];
    const float* be2 = (const float*)d_in[9];
    const float* Wh1 = (const float*)d_in[10];
    const float* bh1 = (const float*)d_in[11];
    const float* Wh2 = (const float*)d_in[12];
    const float* bh2 = (const float*)d_in[13];
    float* out = (float*)d_out;

    __half* bufH;
    float *bufB, *sum1, *sq1, *sum2, *sq2, *sc1, *sh1, *sc2, *sh2;
    cudaGetSymbolAddress((void**)&bufH, g_bufH);
    cudaGetSymbolAddress((void**)&bufB, g_bufB);
    cudaGetSymbolAddress((void**)&sum1, g_sum1);
    cudaGetSymbolAddress((void**)&sq1, g_sq1);
    cudaGetSymbolAddress((void**)&sum2, g_sum2);
    cudaGetSymbolAddress((void**)&sq2, g_sq2);
    cudaGetSymbolAddress((void**)&sc1, g_scale1);
    cudaGetSymbolAddress((void**)&sh1, g_shift1);
    cudaGetSymbolAddress((void**)&sc2, g_scale2);
    cudaGetSymbolAddress((void**)&sh2, g_shift2);

    const int NB = (NNODES + 1023) / 1024;  // 98

    // graph prep (CSR build, shared by both conv layers)
    zero_detect_kernel<<<(NNODES + 255) / 256, 256>>>(ei);
    hist_kernel<<<(NEDGES + 255) / 256, 256>>>(ei);
    scanA_kernel<<<NB, 1024>>>();
    scanB_kernel<<<1, 128>>>(NB);
    scanC_kernel<<<NB, 1024>>>();
    fill_kernel<<<(NEDGES + 255) / 256, 256>>>(ei);

    // layer 1
    gemm_kernel<64, 128, false><<<NNODES / 32, 256>>>(x, W1, bufH, nullptr, nullptr);
    aggregate_kernel<<<NNODES / 16, 512>>>(bufH, b1, bufB, sum1, sq1);
    bn_finalize_kernel<<<1, 128>>>(sum1, sq1, g1, be1, sc1, sh1);

    // layer 2 (BN1+ReLU fused into A-load)
    gemm_kernel<128, 128, true><<<NNODES / 32, 256>>>(bufB, W2, bufH, sc1, sh1);
    aggregate_kernel<<<NNODES / 16, 512>>>(bufH, b2, bufB, sum2, sq2);
    bn_finalize_kernel<<<1, 128>>>(sum2, sq2, g2, be2, sc2, sh2);

    // head (BN2+ReLU + Linear+ReLU + dot + sigmoid fused)
    head_kernel<<<NNODES / 32, 128>>>(bufB, Wh1, bh1, Wh2, bh2, sc2, sh2, out);
}

// round 6
// speedup vs baseline: 1.4082x; 1.0773x over previous
#include <cuda_runtime.h>
#include <cuda_fp16.h>
#include <math.h>

#define NNODES 100000
#define NEDGES 1600000
#define DH 128
#define BN_EPS 1e-5f

typedef unsigned long long u64;

// ---------------- f32x2 packed-FMA helpers (sm_100+) ----------------
__device__ __forceinline__ u64 pack2(float x) {
    u64 r; unsigned u = __float_as_uint(x);
    asm("mov.b64 %0, {%1, %1};" : "=l"(r) : "r"(u));
    return r;
}
__device__ __forceinline__ float2 unpack2(u64 v) {
    unsigned lo, hi;
    asm("mov.b64 {%0, %1}, %2;" : "=r"(lo), "=r"(hi) : "l"(v));
    return make_float2(__uint_as_float(lo), __uint_as_float(hi));
}
__device__ __forceinline__ void fma2(u64& d, u64 a, u64 b) {
    asm("fma.rn.f32x2 %0, %1, %2, %0;" : "+l"(d) : "l"(a), "l"(b));
}

// ---------------- scratch (static __device__, no allocs) ----------------
__device__ __align__(16) __half g_bufH[(size_t)NNODES * DH];  // pre-scaled GEMM out (h' = dinv*h)
__device__ __align__(16) __half g_bufG[(size_t)NNODES * DH];  // aggregate out (fp16)
__device__ int   g_count[NNODES];
__device__ float g_dinv[NNODES];
__device__ int   g_rowstart[NNODES + 1];
__device__ int   g_cursor[NNODES];
__device__ int   g_col[NEDGES];
__device__ float g_sum1[DH], g_sq1[DH], g_sum2[DH], g_sq2[DH];
__device__ int   g_psum[128];
__device__ int   g_is64;

__device__ __forceinline__ int load_idx(const void* ei, long long pos, int is64) {
    return is64 ? (int)((const long long*)ei)[pos] : ((const int*)ei)[pos];
}

// ---------------- utility: block exclusive scan (shfl-based) ----------------
__device__ __forceinline__ int block_excl_scan(int v) {
    const unsigned full = 0xffffffffu;
    int tid = threadIdx.x, lane = tid & 31, wid = tid >> 5;
    int incl = v;
    #pragma unroll
    for (int o = 1; o < 32; o <<= 1) {
        int t = __shfl_up_sync(full, incl, o);
        if (lane >= o) incl += t;
    }
    __shared__ int ws[32];
    if (lane == 31) ws[wid] = incl;
    __syncthreads();
    if (wid == 0) {
        int nw = blockDim.x >> 5;
        int s = (lane < nw) ? ws[lane] : 0;
        #pragma unroll
        for (int o = 1; o < 32; o <<= 1) {
            int t = __shfl_up_sync(full, s, o);
            if (lane >= o) s += t;
        }
        ws[lane] = s;
    }
    __syncthreads();
    int base = wid ? ws[wid - 1] : 0;
    return base + incl - v;
}

// ---------------- graph prep ----------------
__global__ void zero_detect_kernel(const void* ei) {
    int i = blockIdx.x * 256 + threadIdx.x;
    if (i < NNODES) g_count[i] = 0;
    if (i < DH) { g_sum1[i] = 0.f; g_sq1[i] = 0.f; g_sum2[i] = 0.f; g_sq2[i] = 0.f; }
    if (i == 0) {
        // int64 vs int32 transport detection: genuine int64 indices all < NNODES
        const long long* p = (const long long*)ei;
        int ok = 1;
        #pragma unroll
        for (int j = 0; j < 8; j++) {
            long long v = p[j];
            if (v < 0 || v >= NNODES) ok = 0;
        }
        g_is64 = ok;
    }
}

__global__ void hist_kernel(const void* __restrict__ ei) {
    int e = blockIdx.x * 256 + threadIdx.x;
    int is64 = g_is64;
    if (e < NEDGES) {
        int d = load_idx(ei, (long long)NEDGES + e, is64);
        atomicAdd(&g_count[d], 1);
    }
}

// scanA also computes dinv (both read g_count); writes per-block sums
__global__ void scanA_kernel() {
    int i = blockIdx.x * 1024 + threadIdx.x;
    int v = (i < NNODES) ? g_count[i] : 0;
    if (i < NNODES) g_dinv[i] = rsqrtf((float)v + 1.0f);
    const unsigned full = 0xffffffffu;
    int s = v;
    #pragma unroll
    for (int o = 16; o; o >>= 1) s += __shfl_down_sync(full, s, o);
    __shared__ int ws[32];
    int lane = threadIdx.x & 31, wid = threadIdx.x >> 5;
    if (lane == 0) ws[wid] = s;
    __syncthreads();
    if (wid == 0) {
        int t = ws[lane];
        #pragma unroll
        for (int o = 16; o; o >>= 1) t += __shfl_down_sync(full, t, o);
        if (lane == 0) g_psum[blockIdx.x] = t;
    }
}

// scanC: per-element exclusive scan; each block also redundantly reduces
// the per-block partials with j < blockIdx.x (replaces separate scanB launch).
__global__ void scanC_kernel(int nb) {
    int tid = threadIdx.x;
    int i = blockIdx.x * 1024 + tid;
    int v = (i < NNODES) ? g_count[i] : 0;
    int ex = block_excl_scan(v);
    __shared__ int s_base;
    if (tid < 32) {
        int acc = 0;
        for (int j = tid; j < nb; j += 32)
            if (j < blockIdx.x) acc += g_psum[j];
        const unsigned full = 0xffffffffu;
        #pragma unroll
        for (int o = 16; o; o >>= 1) acc += __shfl_down_sync(full, acc, o);
        if (tid == 0) s_base = acc;
    }
    __syncthreads();
    ex += s_base;
    if (i < NNODES) { g_rowstart[i] = ex; g_cursor[i] = ex; }
    if (i == NNODES - 1) g_rowstart[NNODES] = ex + v;
}

__global__ void fill_kernel(const void* __restrict__ ei) {
    int e = blockIdx.x * 256 + threadIdx.x;
    int is64 = g_is64;
    if (e < NEDGES) {
        int s = load_idx(ei, e, is64);
        int d = load_idx(ei, (long long)NEDGES + e, is64);
        int pos = atomicAdd(&g_cursor[d], 1);
        g_col[pos] = s;
    }
}

// ---------------- GEMM1: H'[N,128](fp16) = dinv[row] * (A[N,64](fp32) @ W1) ----------------
__global__ void gemm1_kernel(const float* __restrict__ A, const float* __restrict__ W,
                             __half* __restrict__ C) {
    constexpr int DIN = 64, DOUT = 128, CG = 32, THREADS = 256, BM = 32;
    __shared__ float As[BM * DIN];
    int tid = threadIdx.x;
    size_t r0 = (size_t)blockIdx.x * BM;
    const float4* Ag = (const float4*)(A + r0 * DIN);
    #pragma unroll
    for (int i = tid; i < BM * DIN / 4; i += THREADS) ((float4*)As)[i] = Ag[i];
    __syncthreads();
    int tx = tid % CG, ty = tid / CG;
    u64 acc2[4][2];
    #pragma unroll
    for (int i = 0; i < 4; i++) { acc2[i][0] = 0ull; acc2[i][1] = 0ull; }
    const float* Wp = W + tx * 4;
    #pragma unroll 4
    for (int k = 0; k < DIN; k++) {
        ulonglong2 bv = *(const ulonglong2*)(Wp + (size_t)k * DOUT);
        #pragma unroll
        for (int i = 0; i < 4; i++) {
            u64 aa = pack2(As[(ty * 4 + i) * DIN + k]);
            fma2(acc2[i][0], aa, bv.x);
            fma2(acc2[i][1], aa, bv.y);
        }
    }
    #pragma unroll
    for (int i = 0; i < 4; i++) {
        size_t row = r0 + ty * 4 + i;
        float di = g_dinv[row];
        float2 c01 = unpack2(acc2[i][0]);
        float2 c23 = unpack2(acc2[i][1]);
        __half2 h01 = __floats2half2_rn(c01.x * di, c01.y * di);
        __half2 h23 = __floats2half2_rn(c23.x * di, c23.y * di);
        *(uint2*)(C + row * DOUT + tx * 4) =
            make_uint2(*(unsigned*)&h01, *(unsigned*)&h23);
    }
}

// ---------------- GEMM2: H'[N,128](fp16) = dinv * (bnrelu(A fp16) @ W2) ----------------
// BN scale/shift computed per-block from global sums (replaces bn_finalize launch).
__global__ void gemm2_kernel(const __half* __restrict__ A, const float* __restrict__ W,
                             __half* __restrict__ C,
                             const float* __restrict__ sum, const float* __restrict__ sq,
                             const float* __restrict__ g, const float* __restrict__ be) {
    constexpr int DIN = 128, DOUT = 128, CG = 32, THREADS = 256, BM = 32;
    __shared__ float As[BM * DIN];
    __shared__ float s_scale[DH], s_shift[DH];
    int tid = threadIdx.x;
    if (tid < DH) {
        float m = sum[tid] * (1.0f / NNODES);
        float var = sq[tid] * (1.0f / NNODES) - m * m;
        float inv = rsqrtf(var + BN_EPS);
        float scl = g[tid] * inv;
        s_scale[tid] = scl;
        s_shift[tid] = fmaf(-m, scl, be[tid]);
    }
    __syncthreads();
    size_t r0 = (size_t)blockIdx.x * BM;
    const uint2* Ag = (const uint2*)(A + r0 * DIN);
    #pragma unroll
    for (int i = tid; i < BM * DIN / 4; i += THREADS) {
        uint2 pv = Ag[i];
        float2 v01 = __half22float2(*(__half2*)&pv.x);
        float2 v23 = __half22float2(*(__half2*)&pv.y);
        int c4 = i & (DIN / 4 - 1);
        float4 sc = *(float4*)&s_scale[c4 * 4];
        float4 sh = *(float4*)&s_shift[c4 * 4];
        float4 v;
        v.x = fmaxf(fmaf(v01.x, sc.x, sh.x), 0.f);
        v.y = fmaxf(fmaf(v01.y, sc.y, sh.y), 0.f);
        v.z = fmaxf(fmaf(v23.x, sc.z, sh.z), 0.f);
        v.w = fmaxf(fmaf(v23.y, sc.w, sh.w), 0.f);
        ((float4*)As)[i] = v;
    }
    __syncthreads();
    int tx = tid % CG, ty = tid / CG;
    u64 acc2[4][2];
    #pragma unroll
    for (int i = 0; i < 4; i++) { acc2[i][0] = 0ull; acc2[i][1] = 0ull; }
    const float* Wp = W + tx * 4;
    #pragma unroll 4
    for (int k = 0; k < DIN; k++) {
        ulonglong2 bv = *(const ulonglong2*)(Wp + (size_t)k * DOUT);
        #pragma unroll
        for (int i = 0; i < 4; i++) {
            u64 aa = pack2(As[(ty * 4 + i) * DIN + k]);
            fma2(acc2[i][0], aa, bv.x);
            fma2(acc2[i][1], aa, bv.y);
        }
    }
    #pragma unroll
    for (int i = 0; i < 4; i++) {
        size_t row = r0 + ty * 4 + i;
        float di = g_dinv[row];
        float2 c01 = unpack2(acc2[i][0]);
        float2 c23 = unpack2(acc2[i][1]);
        __half2 h01 = __floats2half2_rn(c01.x * di, c01.y * di);
        __half2 h23 = __floats2half2_rn(c23.x * di, c23.y * di);
        *(uint2*)(C + row * DOUT + tx * 4) =
            make_uint2(*(unsigned*)&h01, *(unsigned*)&h23);
    }
}

// ---------------- aggregation: warp per node, fp16 gather of pre-scaled h' ----------------
// out = dinv[node] * (h'[node] + sum_{c} h'[c]) + bias   (h' already carries dinv[src])
__global__ void aggregate_kernel(const __half* __restrict__ h,
                                 const float* __restrict__ bias,
                                 __half* __restrict__ outb,
                                 float* __restrict__ sum, float* __restrict__ sq) {
    __shared__ float s_sum[16][DH];
    __shared__ float s_sq[16][DH];
    int tid = threadIdx.x;
    int w = tid >> 5, lane = tid & 31;
    int node = blockIdx.x * 16 + w;
    float di = g_dinv[node];
    uint2 sv = ((const uint2*)(h + (size_t)node * DH))[lane];
    float2 f01 = __half22float2(*(__half2*)&sv.x);
    float2 f23 = __half22float2(*(__half2*)&sv.y);
    float a0 = f01.x, a1 = f01.y, a2 = f23.x, a3 = f23.y;
    int e0 = g_rowstart[node], e1 = g_rowstart[node + 1];
    for (int i = e0; i < e1; i++) {
        int c = __ldg(&g_col[i]);
        uint2 vv = ((const uint2*)(h + (size_t)c * DH))[lane];
        float2 v01 = __half22float2(*(__half2*)&vv.x);
        float2 v23 = __half22float2(*(__half2*)&vv.y);
        a0 += v01.x; a1 += v01.y; a2 += v23.x; a3 += v23.y;
    }
    float4 b = ((const float4*)bias)[lane];
    float4 r = make_float4(fmaf(a0, di, b.x), fmaf(a1, di, b.y),
                           fmaf(a2, di, b.z), fmaf(a3, di, b.w));
    __half2 o01 = __floats2half2_rn(r.x, r.y);
    __half2 o23 = __floats2half2_rn(r.z, r.w);
    ((uint2*)(outb + (size_t)node * DH))[lane] =
        make_uint2(*(unsigned*)&o01, *(unsigned*)&o23);
    // per-warp stats partials in fp32 (each lane owns 4 distinct channels)
    *(float4*)&s_sum[w][lane * 4] = r;
    *(float4*)&s_sq[w][lane * 4] =
        make_float4(r.x * r.x, r.y * r.y, r.z * r.z, r.w * r.w);
    __syncthreads();
    if (tid < DH) {
        float a = 0.f, bq = 0.f;
        #pragma unroll
        for (int ww2 = 0; ww2 < 16; ww2++) { a += s_sum[ww2][tid]; bq += s_sq[ww2][tid]; }
        atomicAdd(&sum[tid], a);
        atomicAdd(&sq[tid], bq);
    }
}

// ---------------- fused head: BN2+ReLU -> Linear(128,64)+ReLU -> dot(64)+sigmoid ----------------
__global__ void head_kernel(const __half* __restrict__ A, const float* __restrict__ Wh1,
                            const float* __restrict__ bh1, const float* __restrict__ Wh2,
                            const float* __restrict__ bh2,
                            const float* __restrict__ sum, const float* __restrict__ sq,
                            const float* __restrict__ g, const float* __restrict__ be,
                            float* __restrict__ out) {
    constexpr int DIN = 128, DOUT = 64, CG = 16, THREADS = 128, BM = 32;
    __shared__ float As[BM * DIN];
    __shared__ float s_scale[DH], s_shift[DH];
    int tid = threadIdx.x;
    if (tid < DH) {
        float m = sum[tid] * (1.0f / NNODES);
        float var = sq[tid] * (1.0f / NNODES) - m * m;
        float inv = rsqrtf(var + BN_EPS);
        float scl = g[tid] * inv;
        s_scale[tid] = scl;
        s_shift[tid] = fmaf(-m, scl, be[tid]);
    }
    __syncthreads();
    size_t r0 = (size_t)blockIdx.x * BM;
    const uint2* Ag = (const uint2*)(A + r0 * DIN);
    #pragma unroll
    for (int i = tid; i < BM * DIN / 4; i += THREADS) {
        uint2 pv = Ag[i];
        float2 v01 = __half22float2(*(__half2*)&pv.x);
        float2 v23 = __half22float2(*(__half2*)&pv.y);
        int c4 = i & (DIN / 4 - 1);
        float4 sc = *(float4*)&s_scale[c4 * 4];
        float4 sh = *(float4*)&s_shift[c4 * 4];
        float4 v;
        v.x = fmaxf(fmaf(v01.x, sc.x, sh.x), 0.f);
        v.y = fmaxf(fmaf(v01.y, sc.y, sh.y), 0.f);
        v.z = fmaxf(fmaf(v23.x, sc.z, sh.z), 0.f);
        v.w = fmaxf(fmaf(v23.y, sc.w, sh.w), 0.f);
        ((float4*)As)[i] = v;
    }
    __syncthreads();
    int tx = tid % CG, ty = tid / CG;
    u64 acc2[4][2];
    #pragma unroll
    for (int i = 0; i < 4; i++) { acc2[i][0] = 0ull; acc2[i][1] = 0ull; }
    const float* Wp = Wh1 + tx * 4;
    #pragma unroll 4
    for (int k = 0; k < DIN; k++) {
        ulonglong2 bv = *(const ulonglong2*)(Wp + (size_t)k * DOUT);
        #pragma unroll
        for (int i = 0; i < 4; i++) {
            u64 aa = pack2(As[(ty * 4 + i) * DIN + k]);
            fma2(acc2[i][0], aa, bv.x);
            fma2(acc2[i][1], aa, bv.y);
        }
    }
    const unsigned full = 0xffffffffu;
    float4 bb = ((const float4*)bh1)[tx];
    float4 w2 = ((const float4*)Wh2)[tx];
    float b2v = bh2[0];
    #pragma unroll
    for (int i = 0; i < 4; i++) {
        float2 c01 = unpack2(acc2[i][0]);
        float2 c23 = unpack2(acc2[i][1]);
        float h0 = fmaxf(c01.x + bb.x, 0.f);
        float h1 = fmaxf(c01.y + bb.y, 0.f);
        float h2 = fmaxf(c23.x + bb.z, 0.f);
        float h3 = fmaxf(c23.y + bb.w, 0.f);
        float p = h0 * w2.x + h1 * w2.y + h2 * w2.z + h3 * w2.w;
        p += __shfl_down_sync(full, p, 8, 16);
        p += __shfl_down_sync(full, p, 4, 16);
        p += __shfl_down_sync(full, p, 2, 16);
        p += __shfl_down_sync(full, p, 1, 16);
        if (tx == 0) out[r0 + ty * 4 + i] = 1.0f / (1.0f + __expf(-(p + b2v)));
    }
}

// ---------------- launch ----------------
extern "C" void kernel_launch(void* const* d_in, const int* in_sizes, int n_in,
                              void* d_out, int out_size) {
    const float* x  = (const float*)d_in[0];
    const void*  ei = d_in[1];
    const float* W1 = (const float*)d_in[2];
    const float* b1 = (const float*)d_in[3];
    const float* g1 = (const float*)d_in[4];
    const float* be1 = (const float*)d_in[5];
    const float* W2 = (const float*)d_in[6];
    const float* b2 = (const float*)d_in[7];
    const float* g2 = (const float*)d_in[8];
    const float* be2 = (const float*)d_in[9];
    const float* Wh1 = (const float*)d_in[10];
    const float* bh1 = (const float*)d_in[11];
    const float* Wh2 = (const float*)d_in[12];
    const float* bh2 = (const float*)d_in[13];
    float* out = (float*)d_out;

    __half *bufH, *bufG;
    float *sum1, *sq1, *sum2, *sq2;
    cudaGetSymbolAddress((void**)&bufH, g_bufH);
    cudaGetSymbolAddress((void**)&bufG, g_bufG);
    cudaGetSymbolAddress((void**)&sum1, g_sum1);
    cudaGetSymbolAddress((void**)&sq1, g_sq1);
    cudaGetSymbolAddress((void**)&sum2, g_sum2);
    cudaGetSymbolAddress((void**)&sq2, g_sq2);

    const int NB = (NNODES + 1023) / 1024;  // 98

    // graph prep (CSR build, shared by both conv layers)
    zero_detect_kernel<<<(NNODES + 255) / 256, 256>>>(ei);
    hist_kernel<<<(NEDGES + 255) / 256, 256>>>(ei);
    scanA_kernel<<<NB, 1024>>>();
    scanC_kernel<<<NB, 1024>>>(NB);
    fill_kernel<<<(NEDGES + 255) / 256, 256>>>(ei);

    // layer 1
    gemm1_kernel<<<NNODES / 32, 256>>>(x, W1, bufH);
    aggregate_kernel<<<NNODES / 16, 512>>>(bufH, b1, bufG, sum1, sq1);

    // layer 2 (BN1+ReLU computed in-kernel from sums, fused into A-load)
    gemm2_kernel<<<NNODES / 32, 256>>>(bufG, W2, bufH, sum1, sq1, g1, be1);
    aggregate_kernel<<<NNODES / 16, 512>>>(bufH, b2, bufG, sum2, sq2);

    // head (BN2 + Linear+ReLU + dot + sigmoid fused)
    head_kernel<<<NNODES / 32, 128>>>(bufG, Wh1, bh1, Wh2, bh2, sum2, sq2, g2, be2, out);
}

// round 7
// speedup vs baseline: 1.5148x; 1.0757x over previous
#include <cuda_runtime.h>
#include <cuda_fp16.h>
#include <mma.h>
#include <math.h>

using namespace nvcuda;

#define NNODES 100000
#define NPAD   100032            // 64 * 1563
#define NEDGES 1600000
#define DH 128
#define BN_EPS 1e-5f

typedef unsigned long long u64;

// ---------------- scratch (static __device__, no allocs; zero-initialized) ----------------
__device__ __align__(16) __half g_xh[(size_t)NPAD * 64];      // fp16 x (pad rows zero)
__device__ __align__(16) __half g_bufH[(size_t)NPAD * DH];    // GEMM out (h' = dinv*h), fp16
__device__ __align__(16) __half g_bufG[(size_t)NPAD * DH];    // aggregate out, fp16
__device__ __align__(16) __half g_W1h[64 * 128];
__device__ __align__(16) __half g_W2h[128 * 128];
__device__ __align__(16) __half g_Wh1h[128 * 64];
__device__ int   g_count[NNODES];
__device__ float g_dinv[NPAD];                                // pad entries stay 0
__device__ int   g_rowstart[NNODES + 1];
__device__ int   g_cursor[NNODES];
__device__ int   g_col[NEDGES];
__device__ float g_sum1[DH], g_sq1[DH], g_sum2[DH], g_sq2[DH];
__device__ int   g_psum[128];
__device__ int   g_is64;

__device__ __forceinline__ int load_idx(const void* ei, long long pos, int is64) {
    return is64 ? (int)((const long long*)ei)[pos] : ((const int*)ei)[pos];
}

// ---------------- utility: block exclusive scan (shfl-based) ----------------
__device__ __forceinline__ int block_excl_scan(int v) {
    const unsigned full = 0xffffffffu;
    int tid = threadIdx.x, lane = tid & 31, wid = tid >> 5;
    int incl = v;
    #pragma unroll
    for (int o = 1; o < 32; o <<= 1) {
        int t = __shfl_up_sync(full, incl, o);
        if (lane >= o) incl += t;
    }
    __shared__ int ws[32];
    if (lane == 31) ws[wid] = incl;
    __syncthreads();
    if (wid == 0) {
        int nw = blockDim.x >> 5;
        int s = (lane < nw) ? ws[lane] : 0;
        #pragma unroll
        for (int o = 1; o < 32; o <<= 1) {
            int t = __shfl_up_sync(full, s, o);
            if (lane >= o) s += t;
        }
        ws[lane] = s;
    }
    __syncthreads();
    int base = wid ? ws[wid - 1] : 0;
    return base + incl - v;
}

// ---------------- graph prep ----------------
__global__ void zero_detect_kernel(const void* ei) {
    int i = blockIdx.x * 256 + threadIdx.x;
    if (i < NNODES) g_count[i] = 0;
    if (i < DH) { g_sum1[i] = 0.f; g_sq1[i] = 0.f; g_sum2[i] = 0.f; g_sq2[i] = 0.f; }
    if (i == 0) {
        const long long* p = (const long long*)ei;
        int ok = 1;
        #pragma unroll
        for (int j = 0; j < 8; j++) {
            long long v = p[j];
            if (v < 0 || v >= NNODES) ok = 0;
        }
        g_is64 = ok;
    }
}

// fp16 conversion of x (padded) and the three weight matrices
__global__ void convert_kernel(const float* __restrict__ x,
                               const float* __restrict__ W1,
                               const float* __restrict__ W2,
                               const float* __restrict__ Wh1) {
    int i = blockIdx.x * 256 + threadIdx.x;
    if (i < NPAD * 64)
        g_xh[i] = (i < NNODES * 64) ? __float2half(x[i]) : __float2half(0.f);
    if (i < 64 * 128)  g_W1h[i]  = __float2half(W1[i]);
    if (i < 128 * 128) g_W2h[i]  = __float2half(W2[i]);
    if (i < 128 * 64)  g_Wh1h[i] = __float2half(Wh1[i]);
}

__global__ void hist_kernel(const void* __restrict__ ei) {
    int e = blockIdx.x * 256 + threadIdx.x;
    int is64 = g_is64;
    if (e < NEDGES) {
        int d = load_idx(ei, (long long)NEDGES + e, is64);
        atomicAdd(&g_count[d], 1);
    }
}

__global__ void scanA_kernel() {
    int i = blockIdx.x * 1024 + threadIdx.x;
    int v = (i < NNODES) ? g_count[i] : 0;
    if (i < NNODES) g_dinv[i] = rsqrtf((float)v + 1.0f);
    const unsigned full = 0xffffffffu;
    int s = v;
    #pragma unroll
    for (int o = 16; o; o >>= 1) s += __shfl_down_sync(full, s, o);
    __shared__ int ws[32];
    int lane = threadIdx.x & 31, wid = threadIdx.x >> 5;
    if (lane == 0) ws[wid] = s;
    __syncthreads();
    if (wid == 0) {
        int t = ws[lane];
        #pragma unroll
        for (int o = 16; o; o >>= 1) t += __shfl_down_sync(full, t, o);
        if (lane == 0) g_psum[blockIdx.x] = t;
    }
}

__global__ void scanC_kernel(int nb) {
    int tid = threadIdx.x;
    int i = blockIdx.x * 1024 + tid;
    int v = (i < NNODES) ? g_count[i] : 0;
    int ex = block_excl_scan(v);
    __shared__ int s_base;
    if (tid < 32) {
        int acc = 0;
        for (int j = tid; j < nb; j += 32)
            if (j < blockIdx.x) acc += g_psum[j];
        const unsigned full = 0xffffffffu;
        #pragma unroll
        for (int o = 16; o; o >>= 1) acc += __shfl_down_sync(full, acc, o);
        if (tid == 0) s_base = acc;
    }
    __syncthreads();
    ex += s_base;
    if (i < NNODES) { g_rowstart[i] = ex; g_cursor[i] = ex; }
    if (i == NNODES - 1) g_rowstart[NNODES] = ex + v;
}

__global__ void fill_kernel(const void* __restrict__ ei) {
    int e = blockIdx.x * 256 + threadIdx.x;
    int is64 = g_is64;
    if (e < NEDGES) {
        int s = load_idx(ei, e, is64);
        int d = load_idx(ei, (long long)NEDGES + e, is64);
        int pos = atomicAdd(&g_cursor[d], 1);
        g_col[pos] = s;
    }
}

// ---------------- tensor-core GEMM: C[NPAD,128](fp16) = dinv * (bn?(A) @ W) ----------------
// BM=64, 4 warps, warp w owns rows w*16..+16, all 128 output cols.
// BNIN: BN+ReLU applied while staging A into smem (fp16). Otherwise fragments
// load straight from global A. Accumulators round-trip a smem fp32 tile for
// the dinv-scale + fp16 epilogue (tile overlays the A stage; synced).
template <int K, bool BNIN>
__global__ void wgemm_kernel(const __half* __restrict__ A, const __half* __restrict__ W,
                             __half* __restrict__ C,
                             const float* __restrict__ sum, const float* __restrict__ sq,
                             const float* __restrict__ g, const float* __restrict__ be) {
    constexpr int DOUT = 128, BM = 64, LDC = 132, LDA = K + 8;
    __shared__ __align__(16) char smem_raw[BM * LDC * 4];   // 33.8 KB, As overlays Cs
    __shared__ float s_scale[DH], s_shift[DH];
    float* Cs = (float*)smem_raw;
    __half* As = (__half*)smem_raw;
    int tid = threadIdx.x;
    int w = tid >> 5;
    size_t r0 = (size_t)blockIdx.x * BM;

    if (BNIN) {
        if (tid < DH) {
            float m = sum[tid] * (1.0f / NNODES);
            float var = sq[tid] * (1.0f / NNODES) - m * m;
            float inv = rsqrtf(var + BN_EPS);
            float scl = g[tid] * inv;
            s_scale[tid] = scl;
            s_shift[tid] = fmaf(-m, scl, be[tid]);
        }
        __syncthreads();
        #pragma unroll
        for (int i = tid; i < BM * (K / 4); i += 128) {
            int row = i / (K / 4), c4 = i % (K / 4);
            uint2 pv = *(const uint2*)(A + (r0 + row) * K + c4 * 4);
            float2 v01 = __half22float2(*(__half2*)&pv.x);
            float2 v23 = __half22float2(*(__half2*)&pv.y);
            float4 sc = *(float4*)&s_scale[c4 * 4];
            float4 sh = *(float4*)&s_shift[c4 * 4];
            float o0 = fmaxf(fmaf(v01.x, sc.x, sh.x), 0.f);
            float o1 = fmaxf(fmaf(v01.y, sc.y, sh.y), 0.f);
            float o2 = fmaxf(fmaf(v23.x, sc.z, sh.z), 0.f);
            float o3 = fmaxf(fmaf(v23.y, sc.w, sh.w), 0.f);
            __half2 h01 = __floats2half2_rn(o0, o1);
            __half2 h23 = __floats2half2_rn(o2, o3);
            *(uint2*)(As + row * LDA + c4 * 4) =
                make_uint2(*(unsigned*)&h01, *(unsigned*)&h23);
        }
        __syncthreads();
    }

    wmma::fragment<wmma::accumulator, 16, 16, 16, float> acc[8];
    #pragma unroll
    for (int n = 0; n < 8; n++) wmma::fill_fragment(acc[n], 0.f);
    #pragma unroll
    for (int k = 0; k < K; k += 16) {
        wmma::fragment<wmma::matrix_a, 16, 16, 16, __half, wmma::row_major> fa;
        if (BNIN) wmma::load_matrix_sync(fa, As + (w * 16) * LDA + k, LDA);
        else      wmma::load_matrix_sync(fa, A + (r0 + w * 16) * K + k, K);
        #pragma unroll
        for (int n = 0; n < 8; n++) {
            wmma::fragment<wmma::matrix_b, 16, 16, 16, __half, wmma::row_major> fb;
            wmma::load_matrix_sync(fb, W + k * DOUT + n * 16, DOUT);
            wmma::mma_sync(acc[n], fa, fb, acc[n]);
        }
    }
    __syncthreads();  // everyone done reading As before Cs overwrites it
    #pragma unroll
    for (int n = 0; n < 8; n++)
        wmma::store_matrix_sync(Cs + (w * 16) * LDC + n * 16, acc[n], LDC, wmma::mem_row_major);
    __syncthreads();
    #pragma unroll
    for (int i = tid; i < BM * 32; i += 128) {
        int row = i >> 5, c4 = i & 31;
        float di = g_dinv[r0 + row];
        float4 v = *(float4*)(Cs + row * LDC + c4 * 4);
        __half2 h01 = __floats2half2_rn(v.x * di, v.y * di);
        __half2 h23 = __floats2half2_rn(v.z * di, v.w * di);
        *(uint2*)(C + (r0 + row) * DOUT + c4 * 4) =
            make_uint2(*(unsigned*)&h01, *(unsigned*)&h23);
    }
}

// ---------------- aggregation: warp per node, fp16 gather of pre-scaled h' ----------------
__global__ void aggregate_kernel(const __half* __restrict__ h,
                                 const float* __restrict__ bias,
                                 __half* __restrict__ outb,
                                 float* __restrict__ sum, float* __restrict__ sq) {
    __shared__ float s_sum[16][DH];
    __shared__ float s_sq[16][DH];
    int tid = threadIdx.x;
    int w = tid >> 5, lane = tid & 31;
    int node = blockIdx.x * 16 + w;
    float di = g_dinv[node];
    uint2 sv = ((const uint2*)(h + (size_t)node * DH))[lane];
    float2 f01 = __half22float2(*(__half2*)&sv.x);
    float2 f23 = __half22float2(*(__half2*)&sv.y);
    float a0 = f01.x, a1 = f01.y, a2 = f23.x, a3 = f23.y;
    int e0 = g_rowstart[node], e1 = g_rowstart[node + 1];
    for (int i = e0; i < e1; i++) {
        int c = __ldg(&g_col[i]);
        uint2 vv = ((const uint2*)(h + (size_t)c * DH))[lane];
        float2 v01 = __half22float2(*(__half2*)&vv.x);
        float2 v23 = __half22float2(*(__half2*)&vv.y);
        a0 += v01.x; a1 += v01.y; a2 += v23.x; a3 += v23.y;
    }
    float4 b = ((const float4*)bias)[lane];
    float4 r = make_float4(fmaf(a0, di, b.x), fmaf(a1, di, b.y),
                           fmaf(a2, di, b.z), fmaf(a3, di, b.w));
    __half2 o01 = __floats2half2_rn(r.x, r.y);
    __half2 o23 = __floats2half2_rn(r.z, r.w);
    ((uint2*)(outb + (size_t)node * DH))[lane] =
        make_uint2(*(unsigned*)&o01, *(unsigned*)&o23);
    *(float4*)&s_sum[w][lane * 4] = r;
    *(float4*)&s_sq[w][lane * 4] =
        make_float4(r.x * r.x, r.y * r.y, r.z * r.z, r.w * r.w);
    __syncthreads();
    if (tid < DH) {
        float a = 0.f, bq = 0.f;
        #pragma unroll
        for (int ww2 = 0; ww2 < 16; ww2++) { a += s_sum[ww2][tid]; bq += s_sq[ww2][tid]; }
        atomicAdd(&sum[tid], a);
        atomicAdd(&sq[tid], bq);
    }
}

// ---------------- head: BN2+ReLU -> wmma Linear(128,64) -> +bias,ReLU,dot,sigmoid ----------------
__global__ void whead_kernel(const __half* __restrict__ A, const __half* __restrict__ W,
                             const float* __restrict__ bh1, const float* __restrict__ Wh2,
                             const float* __restrict__ bh2,
                             const float* __restrict__ sum, const float* __restrict__ sq,
                             const float* __restrict__ g, const float* __restrict__ be,
                             float* __restrict__ out) {
    constexpr int K = 128, DOUT = 64, BM = 64, LDA = K + 8, LDC = 68;
    __shared__ __align__(16) char smem_raw[BM * LDA * 2];   // 17.4KB; Cs(64x68 f32) = same size
    __shared__ float s_scale[DH], s_shift[DH];
    __half* As = (__half*)smem_raw;
    float* Cs = (float*)smem_raw;
    int tid = threadIdx.x;
    int w = tid >> 5;
    size_t r0 = (size_t)blockIdx.x * BM;

    if (tid < DH) {
        float m = sum[tid] * (1.0f / NNODES);
        float var = sq[tid] * (1.0f / NNODES) - m * m;
        float inv = rsqrtf(var + BN_EPS);
        float scl = g[tid] * inv;
        s_scale[tid] = scl;
        s_shift[tid] = fmaf(-m, scl, be[tid]);
    }
    __syncthreads();
    #pragma unroll
    for (int i = tid; i < BM * (K / 4); i += 128) {
        int row = i / (K / 4), c4 = i % (K / 4);
        uint2 pv = *(const uint2*)(A + (r0 + row) * K + c4 * 4);
        float2 v01 = __half22float2(*(__half2*)&pv.x);
        float2 v23 = __half22float2(*(__half2*)&pv.y);
        float4 sc = *(float4*)&s_scale[c4 * 4];
        float4 sh = *(float4*)&s_shift[c4 * 4];
        float o0 = fmaxf(fmaf(v01.x, sc.x, sh.x), 0.f);
        float o1 = fmaxf(fmaf(v01.y, sc.y, sh.y), 0.f);
        float o2 = fmaxf(fmaf(v23.x, sc.z, sh.z), 0.f);
        float o3 = fmaxf(fmaf(v23.y, sc.w, sh.w), 0.f);
        __half2 h01 = __floats2half2_rn(o0, o1);
        __half2 h23 = __floats2half2_rn(o2, o3);
        *(uint2*)(As + row * LDA + c4 * 4) =
            make_uint2(*(unsigned*)&h01, *(unsigned*)&h23);
    }
    __syncthreads();

    wmma::fragment<wmma::accumulator, 16, 16, 16, float> acc[4];
    #pragma unroll
    for (int n = 0; n < 4; n++) wmma::fill_fragment(acc[n], 0.f);
    #pragma unroll
    for (int k = 0; k < K; k += 16) {
        wmma::fragment<wmma::matrix_a, 16, 16, 16, __half, wmma::row_major> fa;
        wmma::load_matrix_sync(fa, As + (w * 16) * LDA + k, LDA);
        #pragma unroll
        for (int n = 0; n < 4; n++) {
            wmma::fragment<wmma::matrix_b, 16, 16, 16, __half, wmma::row_major> fb;
            wmma::load_matrix_sync(fb, W + k * DOUT + n * 16, DOUT);
            wmma::mma_sync(acc[n], fa, fb, acc[n]);
        }
    }
    __syncthreads();
    #pragma unroll
    for (int n = 0; n < 4; n++)
        wmma::store_matrix_sync(Cs + (w * 16) * LDC + n * 16, acc[n], LDC, wmma::mem_row_major);
    __syncthreads();
    // epilogue: 2 threads per row, each half the 64-dot
    {
        int row = tid >> 1, jh = (tid & 1) * 32;
        float accv = 0.f;
        #pragma unroll 8
        for (int j = 0; j < 32; j++) {
            float hv = Cs[row * LDC + jh + j];
            hv = fmaxf(hv + __ldg(&bh1[jh + j]), 0.f);
            accv = fmaf(hv, __ldg(&Wh2[jh + j]), accv);
        }
        accv += __shfl_down_sync(0xffffffffu, accv, 1);
        size_t rg = r0 + row;
        if ((tid & 1) == 0 && rg < NNODES)
            out[rg] = 1.0f / (1.0f + __expf(-(accv + bh2[0])));
    }
}

// ---------------- launch ----------------
extern "C" void kernel_launch(void* const* d_in, const int* in_sizes, int n_in,
                              void* d_out, int out_size) {
    const float* x  = (const float*)d_in[0];
    const void*  ei = d_in[1];
    const float* W1 = (const float*)d_in[2];
    const float* b1 = (const float*)d_in[3];
    const float* g1 = (const float*)d_in[4];
    const float* be1 = (const float*)d_in[5];
    const float* W2 = (const float*)d_in[6];
    const float* b2 = (const float*)d_in[7];
    const float* g2 = (const float*)d_in[8];
    const float* be2 = (const float*)d_in[9];
    const float* Wh1 = (const float*)d_in[10];
    const float* bh1 = (const float*)d_in[11];
    const float* Wh2 = (const float*)d_in[12];
    const float* bh2 = (const float*)d_in[13];
    float* out = (float*)d_out;

    __half *xh, *bufH, *bufG, *W1h, *W2h, *Wh1h;
    float *sum1, *sq1, *sum2, *sq2;
    cudaGetSymbolAddress((void**)&xh, g_xh);
    cudaGetSymbolAddress((void**)&bufH, g_bufH);
    cudaGetSymbolAddress((void**)&bufG, g_bufG);
    cudaGetSymbolAddress((void**)&W1h, g_W1h);
    cudaGetSymbolAddress((void**)&W2h, g_W2h);
    cudaGetSymbolAddress((void**)&Wh1h, g_Wh1h);
    cudaGetSymbolAddress((void**)&sum1, g_sum1);
    cudaGetSymbolAddress((void**)&sq1, g_sq1);
    cudaGetSymbolAddress((void**)&sum2, g_sum2);
    cudaGetSymbolAddress((void**)&sq2, g_sq2);

    const int NB = (NNODES + 1023) / 1024;  // 98
    const int NGB = NPAD / 64;              // 1563

    // graph prep + fp16 conversion
    zero_detect_kernel<<<(NNODES + 255) / 256, 256>>>(ei);
    convert_kernel<<<(NPAD * 64) / 256, 256>>>(x, W1, W2, Wh1);
    hist_kernel<<<(NEDGES + 255) / 256, 256>>>(ei);
    scanA_kernel<<<NB, 1024>>>();
    scanC_kernel<<<NB, 1024>>>(NB);
    fill_kernel<<<(NEDGES + 255) / 256, 256>>>(ei);

    // layer 1 (tensor-core GEMM, A direct from global fp16)
    wgemm_kernel<64, false><<<NGB, 128>>>(xh, W1h, bufH,
                                          nullptr, nullptr, nullptr, nullptr);
    aggregate_kernel<<<NNODES / 16, 512>>>(bufH, b1, bufG, sum1, sq1);

    // layer 2 (BN1+ReLU fused into smem A stage)
    wgemm_kernel<128, true><<<NGB, 128>>>(bufG, W2h, bufH, sum1, sq1, g1, be1);
    aggregate_kernel<<<NNODES / 16, 512>>>(bufH, b2, bufG, sum2, sq2);

    // head (BN2 + Linear+ReLU + dot + sigmoid fused)
    whead_kernel<<<NGB, 128>>>(bufG, Wh1h, bh1, Wh2, bh2, sum2, sq2, g2, be2, out);
}

// round 8
// speedup vs baseline: 1.5210x; 1.0041x over previous
#include <cuda_runtime.h>
#include <cuda_fp16.h>
#include <mma.h>
#include <math.h>

using namespace nvcuda;

#define NNODES 100000
#define NPAD   100032            // 64 * 1563
#define NEDGES 1600000
#define DH 128
#define BN_EPS 1e-5f

typedef unsigned long long u64;

// ---------------- scratch (static __device__, no allocs; zero-initialized) ----------------
__device__ __align__(16) __half g_xh[(size_t)NPAD * 64];      // fp16 x (pad rows zero)
__device__ __align__(16) __half g_bufH[(size_t)NPAD * DH];    // GEMM out (h' = dinv*h), fp16
__device__ __align__(16) __half g_bufG[(size_t)NPAD * DH];    // aggregate out, fp16
__device__ __align__(16) __half g_W1h[64 * 128];
__device__ __align__(16) __half g_W2h[128 * 128];
__device__ __align__(16) __half g_Wh1h[128 * 64];
__device__ int   g_count[NNODES];
__device__ float g_dinv[NPAD];                                // pad entries stay 0
__device__ int   g_rowstart[NNODES + 1];
__device__ int   g_cursor[NNODES];
__device__ int   g_col[NEDGES];
__device__ float g_sum1[DH], g_sq1[DH], g_sum2[DH], g_sq2[DH];
__device__ int   g_psum[128];
__device__ int   g_is64;

__device__ __forceinline__ int load_idx(const void* ei, long long pos, int is64) {
    return is64 ? (int)((const long long*)ei)[pos] : ((const int*)ei)[pos];
}

// ---------------- utility: block exclusive scan (shfl-based) ----------------
__device__ __forceinline__ int block_excl_scan(int v) {
    const unsigned full = 0xffffffffu;
    int tid = threadIdx.x, lane = tid & 31, wid = tid >> 5;
    int incl = v;
    #pragma unroll
    for (int o = 1; o < 32; o <<= 1) {
        int t = __shfl_up_sync(full, incl, o);
        if (lane >= o) incl += t;
    }
    __shared__ int ws[32];
    if (lane == 31) ws[wid] = incl;
    __syncthreads();
    if (wid == 0) {
        int nw = blockDim.x >> 5;
        int s = (lane < nw) ? ws[lane] : 0;
        #pragma unroll
        for (int o = 1; o < 32; o <<= 1) {
            int t = __shfl_up_sync(full, s, o);
            if (lane >= o) s += t;
        }
        ws[lane] = s;
    }
    __syncthreads();
    int base = wid ? ws[wid - 1] : 0;
    return base + incl - v;
}

// ---------------- graph prep + fp16 conversion (fused zero/detect/convert) ----------------
__global__ void prep_convert_kernel(const void* ei,
                                    const float* __restrict__ x,
                                    const float* __restrict__ W1,
                                    const float* __restrict__ W2,
                                    const float* __restrict__ Wh1) {
    int i = blockIdx.x * 256 + threadIdx.x;
    if (i < NPAD * 64)
        g_xh[i] = (i < NNODES * 64) ? __float2half(x[i]) : __float2half(0.f);
    if (i < NNODES) g_count[i] = 0;
    if (i < DH) { g_sum1[i] = 0.f; g_sq1[i] = 0.f; g_sum2[i] = 0.f; g_sq2[i] = 0.f; }
    if (i < 64 * 128)  g_W1h[i]  = __float2half(W1[i]);
    if (i < 128 * 128) g_W2h[i]  = __float2half(W2[i]);
    if (i < 128 * 64)  g_Wh1h[i] = __float2half(Wh1[i]);
    if (i == 0) {
        const long long* p = (const long long*)ei;
        int ok = 1;
        #pragma unroll
        for (int j = 0; j < 8; j++) {
            long long v = p[j];
            if (v < 0 || v >= NNODES) ok = 0;
        }
        g_is64 = ok;
    }
}

__global__ void hist_kernel(const void* __restrict__ ei) {
    int e = blockIdx.x * 256 + threadIdx.x;
    int is64 = g_is64;
    if (e < NEDGES) {
        int d = load_idx(ei, (long long)NEDGES + e, is64);
        atomicAdd(&g_count[d], 1);
    }
}

__global__ void scanA_kernel() {
    int i = blockIdx.x * 1024 + threadIdx.x;
    int v = (i < NNODES) ? g_count[i] : 0;
    if (i < NNODES) g_dinv[i] = rsqrtf((float)v + 1.0f);
    const unsigned full = 0xffffffffu;
    int s = v;
    #pragma unroll
    for (int o = 16; o; o >>= 1) s += __shfl_down_sync(full, s, o);
    __shared__ int ws[32];
    int lane = threadIdx.x & 31, wid = threadIdx.x >> 5;
    if (lane == 0) ws[wid] = s;
    __syncthreads();
    if (wid == 0) {
        int t = ws[lane];
        #pragma unroll
        for (int o = 16; o; o >>= 1) t += __shfl_down_sync(full, t, o);
        if (lane == 0) g_psum[blockIdx.x] = t;
    }
}

__global__ void scanC_kernel(int nb) {
    int tid = threadIdx.x;
    int i = blockIdx.x * 1024 + tid;
    int v = (i < NNODES) ? g_count[i] : 0;
    int ex = block_excl_scan(v);
    __shared__ int s_base;
    if (tid < 32) {
        int acc = 0;
        for (int j = tid; j < nb; j += 32)
            if (j < blockIdx.x) acc += g_psum[j];
        const unsigned full = 0xffffffffu;
        #pragma unroll
        for (int o = 16; o; o >>= 1) acc += __shfl_down_sync(full, acc, o);
        if (tid == 0) s_base = acc;
    }
    __syncthreads();
    ex += s_base;
    if (i < NNODES) { g_rowstart[i] = ex; g_cursor[i] = ex; }
    if (i == NNODES - 1) g_rowstart[NNODES] = ex + v;
}

__global__ void fill_kernel(const void* __restrict__ ei) {
    int e = blockIdx.x * 256 + threadIdx.x;
    int is64 = g_is64;
    if (e < NEDGES) {
        int s = load_idx(ei, e, is64);
        int d = load_idx(ei, (long long)NEDGES + e, is64);
        int pos = atomicAdd(&g_cursor[d], 1);
        g_col[pos] = s;
    }
}

// ---------------- tensor-core GEMM: C[NPAD,128](fp16) = dinv * (bn?(A) @ W) ----------------
template <int K, bool BNIN>
__global__ void wgemm_kernel(const __half* __restrict__ A, const __half* __restrict__ W,
                             __half* __restrict__ C,
                             const float* __restrict__ sum, const float* __restrict__ sq,
                             const float* __restrict__ g, const float* __restrict__ be) {
    constexpr int DOUT = 128, BM = 64, LDC = 132, LDA = K + 8;
    __shared__ __align__(16) char smem_raw[BM * LDC * 4];   // 33.8 KB, As overlays Cs
    __shared__ float s_scale[DH], s_shift[DH];
    float* Cs = (float*)smem_raw;
    __half* As = (__half*)smem_raw;
    int tid = threadIdx.x;
    int w = tid >> 5;
    size_t r0 = (size_t)blockIdx.x * BM;

    if (BNIN) {
        if (tid < DH) {
            float m = sum[tid] * (1.0f / NNODES);
            float var = sq[tid] * (1.0f / NNODES) - m * m;
            float inv = rsqrtf(var + BN_EPS);
            float scl = g[tid] * inv;
            s_scale[tid] = scl;
            s_shift[tid] = fmaf(-m, scl, be[tid]);
        }
        __syncthreads();
        #pragma unroll
        for (int i = tid; i < BM * (K / 4); i += 128) {
            int row = i / (K / 4), c4 = i % (K / 4);
            uint2 pv = *(const uint2*)(A + (r0 + row) * K + c4 * 4);
            float2 v01 = __half22float2(*(__half2*)&pv.x);
            float2 v23 = __half22float2(*(__half2*)&pv.y);
            float4 sc = *(float4*)&s_scale[c4 * 4];
            float4 sh = *(float4*)&s_shift[c4 * 4];
            float o0 = fmaxf(fmaf(v01.x, sc.x, sh.x), 0.f);
            float o1 = fmaxf(fmaf(v01.y, sc.y, sh.y), 0.f);
            float o2 = fmaxf(fmaf(v23.x, sc.z, sh.z), 0.f);
            float o3 = fmaxf(fmaf(v23.y, sc.w, sh.w), 0.f);
            __half2 h01 = __floats2half2_rn(o0, o1);
            __half2 h23 = __floats2half2_rn(o2, o3);
            *(uint2*)(As + row * LDA + c4 * 4) =
                make_uint2(*(unsigned*)&h01, *(unsigned*)&h23);
        }
        __syncthreads();
    }

    wmma::fragment<wmma::accumulator, 16, 16, 16, float> acc[8];
    #pragma unroll
    for (int n = 0; n < 8; n++) wmma::fill_fragment(acc[n], 0.f);
    #pragma unroll
    for (int k = 0; k < K; k += 16) {
        wmma::fragment<wmma::matrix_a, 16, 16, 16, __half, wmma::row_major> fa;
        if (BNIN) wmma::load_matrix_sync(fa, As + (w * 16) * LDA + k, LDA);
        else      wmma::load_matrix_sync(fa, A + (r0 + w * 16) * K + k, K);
        #pragma unroll
        for (int n = 0; n < 8; n++) {
            wmma::fragment<wmma::matrix_b, 16, 16, 16, __half, wmma::row_major> fb;
            wmma::load_matrix_sync(fb, W + k * DOUT + n * 16, DOUT);
            wmma::mma_sync(acc[n], fa, fb, acc[n]);
        }
    }
    __syncthreads();
    #pragma unroll
    for (int n = 0; n < 8; n++)
        wmma::store_matrix_sync(Cs + (w * 16) * LDC + n * 16, acc[n], LDC, wmma::mem_row_major);
    __syncthreads();
    #pragma unroll
    for (int i = tid; i < BM * 32; i += 128) {
        int row = i >> 5, c4 = i & 31;
        float di = g_dinv[r0 + row];
        float4 v = *(float4*)(Cs + row * LDC + c4 * 4);
        __half2 h01 = __floats2half2_rn(v.x * di, v.y * di);
        __half2 h23 = __floats2half2_rn(v.z * di, v.w * di);
        *(uint2*)(C + (r0 + row) * DOUT + c4 * 4) =
            make_uint2(*(unsigned*)&h01, *(unsigned*)&h23);
    }
}

// ---------------- aggregation: warp per node, software-pipelined fp16 gather ----------------
// Inner loop: prefetch next col index while gathering current rows; 2 edges per
// iteration with independent accumulators (MLP >= 2, breaks the col->row chain).
__global__ void aggregate_kernel(const __half* __restrict__ h,
                                 const float* __restrict__ bias,
                                 __half* __restrict__ outb,
                                 float* __restrict__ sum, float* __restrict__ sq) {
    __shared__ float s_sum[16][DH];
    __shared__ float s_sq[16][DH];
    int tid = threadIdx.x;
    int w = tid >> 5, lane = tid & 31;
    int node = blockIdx.x * 16 + w;
    float di = g_dinv[node];
    uint2 sv = ((const uint2*)(h + (size_t)node * DH))[lane];
    float2 f01 = __half22float2(*(__half2*)&sv.x);
    float2 f23 = __half22float2(*(__half2*)&sv.y);
    float a0 = f01.x, a1 = f01.y, a2 = f23.x, a3 = f23.y;
    float b0 = 0.f, b1v = 0.f, b2v = 0.f, b3 = 0.f;
    int e0 = g_rowstart[node], e1 = g_rowstart[node + 1];
    int i = e0;
    int c0 = 0, c1 = 0;
    if (i < e1) c0 = __ldg(&g_col[i]);
    if (i + 1 < e1) c1 = __ldg(&g_col[i + 1]);
    for (; i + 2 <= e1; i += 2) {
        // issue both gathers + next two col loads before consuming anything
        uint2 v0 = ((const uint2*)(h + (size_t)c0 * DH))[lane];
        uint2 v1 = ((const uint2*)(h + (size_t)c1 * DH))[lane];
        int cn0 = 0, cn1 = 0;
        if (i + 2 < e1) cn0 = __ldg(&g_col[i + 2]);
        if (i + 3 < e1) cn1 = __ldg(&g_col[i + 3]);
        float2 p01 = __half22float2(*(__half2*)&v0.x);
        float2 p23 = __half22float2(*(__half2*)&v0.y);
        a0 += p01.x; a1 += p01.y; a2 += p23.x; a3 += p23.y;
        float2 q01 = __half22float2(*(__half2*)&v1.x);
        float2 q23 = __half22float2(*(__half2*)&v1.y);
        b0 += q01.x; b1v += q01.y; b2v += q23.x; b3 += q23.y;
        c0 = cn0; c1 = cn1;
    }
    if (i < e1) {
        uint2 v0 = ((const uint2*)(h + (size_t)c0 * DH))[lane];
        float2 p01 = __half22float2(*(__half2*)&v0.x);
        float2 p23 = __half22float2(*(__half2*)&v0.y);
        a0 += p01.x; a1 += p01.y; a2 += p23.x; a3 += p23.y;
    }
    a0 += b0; a1 += b1v; a2 += b2v; a3 += b3;
    float4 b = ((const float4*)bias)[lane];
    float4 r = make_float4(fmaf(a0, di, b.x), fmaf(a1, di, b.y),
                           fmaf(a2, di, b.z), fmaf(a3, di, b.w));
    __half2 o01 = __floats2half2_rn(r.x, r.y);
    __half2 o23 = __floats2half2_rn(r.z, r.w);
    ((uint2*)(outb + (size_t)node * DH))[lane] =
        make_uint2(*(unsigned*)&o01, *(unsigned*)&o23);
    *(float4*)&s_sum[w][lane * 4] = r;
    *(float4*)&s_sq[w][lane * 4] =
        make_float4(r.x * r.x, r.y * r.y, r.z * r.z, r.w * r.w);
    __syncthreads();
    if (tid < DH) {
        float a = 0.f, bq = 0.f;
        #pragma unroll
        for (int ww2 = 0; ww2 < 16; ww2++) { a += s_sum[ww2][tid]; bq += s_sq[ww2][tid]; }
        atomicAdd(&sum[tid], a);
        atomicAdd(&sq[tid], bq);
    }
}

// ---------------- head: BN2+ReLU -> wmma Linear(128,64) -> +bias,ReLU,dot,sigmoid ----------------
__global__ void whead_kernel(const __half* __restrict__ A, const __half* __restrict__ W,
                             const float* __restrict__ bh1, const float* __restrict__ Wh2,
                             const float* __restrict__ bh2,
                             const float* __restrict__ sum, const float* __restrict__ sq,
                             const float* __restrict__ g, const float* __restrict__ be,
                             float* __restrict__ out) {
    constexpr int K = 128, DOUT = 64, BM = 64, LDA = K + 8, LDC = 68;
    __shared__ __align__(16) char smem_raw[BM * LDA * 2];
    __shared__ float s_scale[DH], s_shift[DH];
    __half* As = (__half*)smem_raw;
    float* Cs = (float*)smem_raw;
    int tid = threadIdx.x;
    int w = tid >> 5;
    size_t r0 = (size_t)blockIdx.x * BM;

    if (tid < DH) {
        float m = sum[tid] * (1.0f / NNODES);
        float var = sq[tid] * (1.0f / NNODES) - m * m;
        float inv = rsqrtf(var + BN_EPS);
        float scl = g[tid] * inv;
        s_scale[tid] = scl;
        s_shift[tid] = fmaf(-m, scl, be[tid]);
    }
    __syncthreads();
    #pragma unroll
    for (int i = tid; i < BM * (K / 4); i += 128) {
        int row = i / (K / 4), c4 = i % (K / 4);
        uint2 pv = *(const uint2*)(A + (r0 + row) * K + c4 * 4);
        float2 v01 = __half22float2(*(__half2*)&pv.x);
        float2 v23 = __half22float2(*(__half2*)&pv.y);
        float4 sc = *(float4*)&s_scale[c4 * 4];
        float4 sh = *(float4*)&s_shift[c4 * 4];
        float o0 = fmaxf(fmaf(v01.x, sc.x, sh.x), 0.f);
        float o1 = fmaxf(fmaf(v01.y, sc.y, sh.y), 0.f);
        float o2 = fmaxf(fmaf(v23.x, sc.z, sh.z), 0.f);
        float o3 = fmaxf(fmaf(v23.y, sc.w, sh.w), 0.f);
        __half2 h01 = __floats2half2_rn(o0, o1);
        __half2 h23 = __floats2half2_rn(o2, o3);
        *(uint2*)(As + row * LDA + c4 * 4) =
            make_uint2(*(unsigned*)&h01, *(unsigned*)&h23);
    }
    __syncthreads();

    wmma::fragment<wmma::accumulator, 16, 16, 16, float> acc[4];
    #pragma unroll
    for (int n = 0; n < 4; n++) wmma::fill_fragment(acc[n], 0.f);
    #pragma unroll
    for (int k = 0; k < K; k += 16) {
        wmma::fragment<wmma::matrix_a, 16, 16, 16, __half, wmma::row_major> fa;
        wmma::load_matrix_sync(fa, As + (w * 16) * LDA + k, LDA);
        #pragma unroll
        for (int n = 0; n < 4; n++) {
            wmma::fragment<wmma::matrix_b, 16, 16, 16, __half, wmma::row_major> fb;
            wmma::load_matrix_sync(fb, W + k * DOUT + n * 16, DOUT);
            wmma::mma_sync(acc[n], fa, fb, acc[n]);
        }
    }
    __syncthreads();
    #pragma unroll
    for (int n = 0; n < 4; n++)
        wmma::store_matrix_sync(Cs + (w * 16) * LDC + n * 16, acc[n], LDC, wmma::mem_row_major);
    __syncthreads();
    {
        int row = tid >> 1, jh = (tid & 1) * 32;
        float accv = 0.f;
        #pragma unroll 8
        for (int j = 0; j < 32; j++) {
            float hv = Cs[row * LDC + jh + j];
            hv = fmaxf(hv + __ldg(&bh1[jh + j]), 0.f);
            accv = fmaf(hv, __ldg(&Wh2[jh + j]), accv);
        }
        accv += __shfl_down_sync(0xffffffffu, accv, 1);
        size_t rg = r0 + row;
        if ((tid & 1) == 0 && rg < NNODES)
            out[rg] = 1.0f / (1.0f + __expf(-(accv + bh2[0])));
    }
}

// ---------------- launch ----------------
extern "C" void kernel_launch(void* const* d_in, const int* in_sizes, int n_in,
                              void* d_out, int out_size) {
    const float* x  = (const float*)d_in[0];
    const void*  ei = d_in[1];
    const float* W1 = (const float*)d_in[2];
    const float* b1 = (const float*)d_in[3];
    const float* g1 = (const float*)d_in[4];
    const float* be1 = (const float*)d_in[5];
    const float* W2 = (const float*)d_in[6];
    const float* b2 = (const float*)d_in[7];
    const float* g2 = (const float*)d_in[8];
    const float* be2 = (const float*)d_in[9];
    const float* Wh1 = (const float*)d_in[10];
    const float* bh1 = (const float*)d_in[11];
    const float* Wh2 = (const float*)d_in[12];
    const float* bh2 = (const float*)d_in[13];
    float* out = (float*)d_out;

    __half *xh, *bufH, *bufG, *W1h, *W2h, *Wh1h;
    float *sum1, *sq1, *sum2, *sq2;
    cudaGetSymbolAddress((void**)&xh, g_xh);
    cudaGetSymbolAddress((void**)&bufH, g_bufH);
    cudaGetSymbolAddress((void**)&bufG, g_bufG);
    cudaGetSymbolAddress((void**)&W1h, g_W1h);
    cudaGetSymbolAddress((void**)&W2h, g_W2h);
    cudaGetSymbolAddress((void**)&Wh1h, g_Wh1h);
    cudaGetSymbolAddress((void**)&sum1, g_sum1);
    cudaGetSymbolAddress((void**)&sq1, g_sq1);
    cudaGetSymbolAddress((void**)&sum2, g_sum2);
    cudaGetSymbolAddress((void**)&sq2, g_sq2);

    const int NB = (NNODES + 1023) / 1024;  // 98
    const int NGB = NPAD / 64;              // 1563

    // graph prep + fp16 conversion (fused)
    prep_convert_kernel<<<(NPAD * 64) / 256, 256>>>(ei, x, W1, W2, Wh1);
    hist_kernel<<<(NEDGES + 255) / 256, 256>>>(ei);
    scanA_kernel<<<NB, 1024>>>();
    scanC_kernel<<<NB, 1024>>>(NB);
    fill_kernel<<<(NEDGES + 255) / 256, 256>>>(ei);

    // layer 1 (tensor-core GEMM, A direct from global fp16)
    wgemm_kernel<64, false><<<NGB, 128>>>(xh, W1h, bufH,
                                          nullptr, nullptr, nullptr, nullptr);
    aggregate_kernel<<<NNODES / 16, 512>>>(bufH, b1, bufG, sum1, sq1);

    // layer 2 (BN1+ReLU fused into smem A stage)
    wgemm_kernel<128, true><<<NGB, 128>>>(bufG, W2h, bufH, sum1, sq1, g1, be1);
    aggregate_kernel<<<NNODES / 16, 512>>>(bufH, b2, bufG, sum2, sq2);

    // head (BN2 + Linear+ReLU + dot + sigmoid fused)
    whead_kernel<<<NGB, 128>>>(bufG, Wh1h, bh1, Wh2, bh2, sum2, sq2, g2, be2, out);
}